// round 5
// baseline (speedup 1.0000x reference)
#include <cuda_runtime.h>
#include <cstdint>

// FAVOR+ attention via mma.sync tf32, pre-converted operands + paired-fragment
// smem layouts. B=4, L=4096, D=1024, H=16 x d=64, m=256.

namespace {
constexpr int L_ = 4096, D_ = 1024;
constexpr float SCALE = 0.17677669529663687f, SC2 = SCALE * SCALE;
constexpr float CEPS = 1e-4f, INVSQM = 0.0625f;
// favor_k smem (float/uint32 offsets)
constexpr int KW = 0;          // W    [256 f][72]  (d perm)
constexpr int KX = 18432;      // K    [128 l][72]  (d perm)
constexpr int KVo = 27648;     // V^T  [72 d'][136] (l perm; row 64 = ones)
constexpr int KP = 37440;      // k'   [128 f][136] (l perm)
constexpr int KH = 54848;      // eb[128]
constexpr int KFL = 54976;     // 219904 B
// favor_q smem
constexpr int QW = 0;          // W    [256 f][72]
constexpr int QP = 18432;      // Q [64][72] overlaid, then q' [64 l][264] (f perm)
constexpr int QKV = 35328;     // KV^T [72 d'][264] (f perm)
constexpr int QDEN = 54336;    // den[64]
constexpr int QFL = 54400;     // 217600 B
}

__device__ float g_kv[64 * 256 * 72];   // [bh][f][d'(64=ksum)]
__device__ unsigned g_min_ss;

__device__ __forceinline__ int p8(int j) { return ((j & 3) * 2) | (j >> 2); }
__device__ __forceinline__ uint32_t cvt_tf32(float x) {
    uint32_t r;
    asm("cvt.rna.tf32.f32 %0, %1;" : "=r"(r) : "f"(x));
    return r;
}
__device__ __forceinline__ void mma8(float* c, const uint32_t* a, const uint32_t* b) {
    asm volatile(
        "mma.sync.aligned.m16n8k8.row.col.f32.tf32.tf32.f32 "
        "{%0,%1,%2,%3},{%4,%5,%6,%7},{%8,%9},{%0,%1,%2,%3};"
        : "+f"(c[0]), "+f"(c[1]), "+f"(c[2]), "+f"(c[3])
        : "r"(a[0]), "r"(a[1]), "r"(a[2]), "r"(a[3]), "r"(b[0]), "r"(b[1]));
}

// ---------------------------------------------------------------------------
__global__ void zero_kernel() {
    size_t tid = (size_t)blockIdx.x * blockDim.x + threadIdx.x;
    size_t stride = (size_t)gridDim.x * blockDim.x;
    constexpr size_t n = (size_t)64 * 256 * 72;
    for (size_t i = tid; i < n; i += stride) g_kv[i] = 0.f;
    if (tid == 0) g_min_ss = 0x7F800000u;
}

__global__ __launch_bounds__(256) void min_kernel(const float* __restrict__ Kp) {
    int t = threadIdx.x;
    float mn = 3.4028235e38f;
#pragma unroll
    for (int it = 0; it < 16; ++it) {
        size_t ch = (size_t)blockIdx.x * 256 + it * 16 + (t >> 4);
        float4 v4 = *reinterpret_cast<const float4*>(Kp + ch * 64 + (t & 15) * 4);
        float ss = v4.x * v4.x + v4.y * v4.y + v4.z * v4.z + v4.w * v4.w;
        ss += __shfl_xor_sync(~0u, ss, 8); ss += __shfl_xor_sync(~0u, ss, 4);
        ss += __shfl_xor_sync(~0u, ss, 2); ss += __shfl_xor_sync(~0u, ss, 1);
        mn = fminf(mn, ss);
    }
    mn = fminf(mn, __shfl_xor_sync(~0u, mn, 16));
    __shared__ float wmin[8];
    if ((t & 31) == 0) wmin[t >> 5] = mn;
    __syncthreads();
    if (t < 8) {
        float m2 = wmin[t];
        m2 = fminf(m2, __shfl_xor_sync(0xffu, m2, 4));
        m2 = fminf(m2, __shfl_xor_sync(0xffu, m2, 2));
        m2 = fminf(m2, __shfl_xor_sync(0xffu, m2, 1));
        if (t == 0) atomicMin(&g_min_ss, __float_as_uint(m2));
    }
}

// ---------------------------------------------------------------------------
__global__ __launch_bounds__(256, 1) void favor_k(
    const float* __restrict__ K_, const float* __restrict__ V_,
    const float* __restrict__ W_) {
    extern __shared__ float s[];
    uint32_t* su = reinterpret_cast<uint32_t*>(s);
    const int t = threadIdx.x, w = t >> 5;
    const int qrow = (t & 31) >> 2, qcol = t & 3;
    const int bh = blockIdx.x, bb = bh >> 4, hh = bh & 15;
#pragma unroll
    for (int i = 0; i < 16; ++i) {   // W -> tf32 bits, d-permuted
        int idx = t + i * 256, f = idx >> 4, c4 = idx & 15;
        float4 wv = *reinterpret_cast<const float4*>(W_ + f * 64 + c4 * 4);
        uint32_t* dst = su + KW + f * 72 + (c4 >> 1) * 8 + (c4 & 1);
        dst[0] = cvt_tf32(wv.x); dst[2] = cvt_tf32(wv.y);
        dst[4] = cvt_tf32(wv.z); dst[6] = cvt_tf32(wv.w);
    }
    if (t < 128) {   // Vaug pad rows (constant, perm-invariant)
        const uint32_t one = cvt_tf32(1.f);
#pragma unroll
        for (int r = 64; r < 72; ++r) su[KVo + r * 136 + t] = (r == 64) ? one : 0u;
    }
    const float stab = -0.5f * SC2 * __uint_as_float(g_min_ss);
    float kvacc[2][9][4] = {};
    __syncthreads();
    const int mbase = (w >> 1) * 32, nb = (w & 1) * 64;
    const int pr = p8(qrow);

    for (int ti = 0; ti < 8; ++ti) {
        const int l0 = ((int)blockIdx.y * 8 + ti) * 128;
#pragma unroll
        for (int i = 0; i < 8; ++i) {
            int idx = t + i * 256, l = idx >> 4, c4 = idx & 15;
            size_t off = ((size_t)(bb * L_ + l0 + l)) * D_ + hh * 64 + c4 * 4;
            float4 kk = *reinterpret_cast<const float4*>(K_ + off);
            uint32_t* dst = su + KX + l * 72 + (c4 >> 1) * 8 + (c4 & 1);
            dst[0] = cvt_tf32(kk.x); dst[2] = cvt_tf32(kk.y);
            dst[4] = cvt_tf32(kk.z); dst[6] = cvt_tf32(kk.w);
            float ss = kk.x * kk.x + kk.y * kk.y + kk.z * kk.z + kk.w * kk.w;
            ss += __shfl_xor_sync(~0u, ss, 1);
            ss += __shfl_xor_sync(~0u, ss, 2);
            ss += __shfl_xor_sync(~0u, ss, 4);
            ss += __shfl_xor_sync(~0u, ss, 8);
            if ((t & 15) == 0) s[KH + l] = fmaf(-0.5f * SC2, ss, -stab);
            float4 vv = *reinterpret_cast<const float4*>(V_ + off);
            int lp = (l & ~7) | p8(l & 7);
            int d0 = c4 * 4;
            su[KVo + (d0 + 0) * 136 + lp] = cvt_tf32(vv.x);
            su[KVo + (d0 + 1) * 136 + lp] = cvt_tf32(vv.y);
            su[KVo + (d0 + 2) * 136 + lp] = cvt_tf32(vv.z);
            su[KVo + (d0 + 3) * 136 + lp] = cvt_tf32(vv.w);
        }
        __syncthreads();

#pragma unroll
        for (int h = 0; h < 2; ++h) {
            // ---- GEMM1: S[128, 128 f-half] = K x W^T ----
            float c[2][8][4] = {};
#pragma unroll
            for (int ks = 0; ks < 8; ++ks) {
                uint32_t a[2][4];
#pragma unroll
                for (int mi = 0; mi < 2; ++mi) {
                    const uint32_t* ap = su + KX + (mbase + mi * 16 + qrow) * 72 + ks * 8 + 2 * qcol;
                    uint2 lo = *reinterpret_cast<const uint2*>(ap);
                    uint2 hi = *reinterpret_cast<const uint2*>(ap + 8 * 72);
                    a[mi][0] = lo.x; a[mi][1] = hi.x; a[mi][2] = lo.y; a[mi][3] = hi.y;
                }
#pragma unroll
                for (int ni = 0; ni < 8; ++ni) {
                    const uint32_t* bp = su + KW + (h * 128 + nb + ni * 8 + qrow) * 72 + ks * 8 + 2 * qcol;
                    uint2 bv = *reinterpret_cast<const uint2*>(bp);
                    uint32_t b2[2] = {bv.x, bv.y};
                    mma8(c[0][ni], a[0], b2);
                    mma8(c[1][ni], a[1], b2);
                }
            }
            // ---- epilogue: k' -> KP[f][l-perm], tf32 bits ----
#pragma unroll
            for (int mi = 0; mi < 2; ++mi) {
                int r0 = mbase + mi * 16 + qrow;
                float eb0 = s[KH + r0], eb1 = s[KH + r0 + 8];
                int colA = (mbase + mi * 16) + pr;
#pragma unroll
                for (int ni = 0; ni < 8; ++ni) {
                    int fh = nb + ni * 8 + qcol * 2;
                    su[KP + fh * 136 + colA] =
                        cvt_tf32(INVSQM * (__expf(fmaf(SCALE, c[mi][ni][0], eb0)) + CEPS));
                    su[KP + (fh + 1) * 136 + colA] =
                        cvt_tf32(INVSQM * (__expf(fmaf(SCALE, c[mi][ni][1], eb0)) + CEPS));
                    su[KP + fh * 136 + colA + 8] =
                        cvt_tf32(INVSQM * (__expf(fmaf(SCALE, c[mi][ni][2], eb1)) + CEPS));
                    su[KP + (fh + 1) * 136 + colA + 8] =
                        cvt_tf32(INVSQM * (__expf(fmaf(SCALE, c[mi][ni][3], eb1)) + CEPS));
                }
            }
            __syncthreads();
            // ---- GEMM2: KV[f,72] += k'^T x Vaug ----
#pragma unroll
            for (int ks = 0; ks < 16; ++ks) {
                const uint32_t* ap = su + KP + (w * 16 + qrow) * 136 + ks * 8 + 2 * qcol;
                uint2 lo = *reinterpret_cast<const uint2*>(ap);
                uint2 hi = *reinterpret_cast<const uint2*>(ap + 8 * 136);
                uint32_t a2[4] = {lo.x, hi.x, lo.y, hi.y};
#pragma unroll
                for (int ni = 0; ni < 9; ++ni) {
                    const uint32_t* bp = su + KVo + (ni * 8 + qrow) * 136 + ks * 8 + 2 * qcol;
                    uint2 bv = *reinterpret_cast<const uint2*>(bp);
                    uint32_t b2[2] = {bv.x, bv.y};
                    mma8(kvacc[h][ni], a2, b2);
                }
            }
            __syncthreads();
        }
    }
    float* g = g_kv + (size_t)bh * 256 * 72;
#pragma unroll
    for (int h = 0; h < 2; ++h)
#pragma unroll
        for (int ni = 0; ni < 9; ++ni) {
            int f0 = h * 128 + w * 16 + qrow, d0 = ni * 8 + qcol * 2;
            atomicAdd(g + f0 * 72 + d0, kvacc[h][ni][0]);
            atomicAdd(g + f0 * 72 + d0 + 1, kvacc[h][ni][1]);
            atomicAdd(g + (f0 + 8) * 72 + d0, kvacc[h][ni][2]);
            atomicAdd(g + (f0 + 8) * 72 + d0 + 1, kvacc[h][ni][3]);
        }
}

// ---------------------------------------------------------------------------
__global__ __launch_bounds__(256, 1) void favor_q(
    const float* __restrict__ Q_, const float* __restrict__ W_,
    float* __restrict__ O_) {
    extern __shared__ float s[];
    uint32_t* su = reinterpret_cast<uint32_t*>(s);
    const int t = threadIdx.x, w = t >> 5;
    const int qrow = (t & 31) >> 2, qcol = t & 3;
    const int bh = blockIdx.x, bb = bh >> 4, hh = bh & 15;
#pragma unroll
    for (int i = 0; i < 16; ++i) {
        int idx = t + i * 256, f = idx >> 4, c4 = idx & 15;
        float4 wv = *reinterpret_cast<const float4*>(W_ + f * 64 + c4 * 4);
        uint32_t* dst = su + QW + f * 72 + (c4 >> 1) * 8 + (c4 & 1);
        dst[0] = cvt_tf32(wv.x); dst[2] = cvt_tf32(wv.y);
        dst[4] = cvt_tf32(wv.z); dst[6] = cvt_tf32(wv.w);
    }
    {   // KV^T [d'][f-perm], tf32 bits, coalesced read
        const float* g = g_kv + (size_t)bh * 256 * 72;
        for (int i = t; i < 256 * 72; i += 256) {
            int f = i / 72, d = i - f * 72;
            su[QKV + d * 264 + (f & ~7) + p8(f & 7)] = cvt_tf32(g[i]);
        }
    }
    __syncthreads();
    const int mbase = (w >> 2) * 32, nb = (w & 3) * 64;
    const int lb = (w >> 1) * 16, nh = w & 1;
    const int nf = nh ? 4 : 5, nb3 = nh ? 40 : 0;
    const int pe = p8((qcol * 2) & 7), po = p8((qcol * 2 + 1) & 7);

    for (int ti = 0; ti < 16; ++ti) {
        const int l0 = ((int)blockIdx.y * 16 + ti) * 64;
#pragma unroll
        for (int i = 0; i < 4; ++i) {
            int idx = t + i * 256, l = idx >> 4, c4 = idx & 15;
            size_t off = ((size_t)(bb * L_ + l0 + l)) * D_ + hh * 64 + c4 * 4;
            float4 qq = *reinterpret_cast<const float4*>(Q_ + off);
            uint32_t* dst = su + QP + l * 72 + (c4 >> 1) * 8 + (c4 & 1);
            dst[0] = cvt_tf32(qq.x); dst[2] = cvt_tf32(qq.y);
            dst[4] = cvt_tf32(qq.z); dst[6] = cvt_tf32(qq.w);
        }
        __syncthreads();
        // ---- GEMM1: S[64, 256] = Q x W^T ----
        float c[2][8][4] = {};
#pragma unroll
        for (int ks = 0; ks < 8; ++ks) {
            uint32_t a[2][4];
#pragma unroll
            for (int mi = 0; mi < 2; ++mi) {
                const uint32_t* ap = su + QP + (mbase + mi * 16 + qrow) * 72 + ks * 8 + 2 * qcol;
                uint2 lo = *reinterpret_cast<const uint2*>(ap);
                uint2 hi = *reinterpret_cast<const uint2*>(ap + 8 * 72);
                a[mi][0] = lo.x; a[mi][1] = hi.x; a[mi][2] = lo.y; a[mi][3] = hi.y;
            }
#pragma unroll
            for (int ni = 0; ni < 8; ++ni) {
                const uint32_t* bp = su + QW + (nb + ni * 8 + qrow) * 72 + ks * 8 + 2 * qcol;
                uint2 bv = *reinterpret_cast<const uint2*>(bp);
                uint32_t b2[2] = {bv.x, bv.y};
                mma8(c[0][ni], a[0], b2);
                mma8(c[1][ni], a[1], b2);
            }
        }
        __syncthreads();   // Q tile dead; q' overwrites region
        // ---- epilogue: q' -> QP[l][f-perm], tf32 bits ----
#pragma unroll
        for (int mi = 0; mi < 2; ++mi) {
            int r0 = mbase + mi * 16 + qrow;
#pragma unroll
            for (int ni = 0; ni < 8; ++ni) {
                int fg = nb + ni * 8;
                su[QP + r0 * 264 + fg + pe] = cvt_tf32(INVSQM * (__expf(SCALE * c[mi][ni][0]) + CEPS));
                su[QP + r0 * 264 + fg + po] = cvt_tf32(INVSQM * (__expf(SCALE * c[mi][ni][1]) + CEPS));
                su[QP + (r0 + 8) * 264 + fg + pe] = cvt_tf32(INVSQM * (__expf(SCALE * c[mi][ni][2]) + CEPS));
                su[QP + (r0 + 8) * 264 + fg + po] = cvt_tf32(INVSQM * (__expf(SCALE * c[mi][ni][3]) + CEPS));
            }
        }
        __syncthreads();
        // ---- GEMM3: out[64, 72] = q' x KV^T ----
        float o[5][4] = {};
#pragma unroll
        for (int ks = 0; ks < 32; ++ks) {
            const uint32_t* ap = su + QP + (lb + qrow) * 264 + ks * 8 + 2 * qcol;
            uint2 lo = *reinterpret_cast<const uint2*>(ap);
            uint2 hi = *reinterpret_cast<const uint2*>(ap + 8 * 264);
            uint32_t a2[4] = {lo.x, hi.x, lo.y, hi.y};
#pragma unroll
            for (int ni = 0; ni < 5; ++ni)
                if (ni < nf) {
                    const uint32_t* bp = su + QKV + (nb3 + ni * 8 + qrow) * 264 + ks * 8 + 2 * qcol;
                    uint2 bv = *reinterpret_cast<const uint2*>(bp);
                    uint32_t b2[2] = {bv.x, bv.y};
                    mma8(o[ni], a2, b2);
                }
        }
        if (nh == 1 && qcol == 0) {   // col 64 = denominator
            s[QDEN + lb + qrow] = o[3][0];
            s[QDEN + lb + qrow + 8] = o[3][2];
        }
        __syncthreads();
        float dv0 = s[QDEN + lb + qrow], dv1 = s[QDEN + lb + qrow + 8];
        if (fabsf(dv0) <= CEPS) dv0 += 2.f * CEPS;
        if (fabsf(dv1) <= CEPS) dv1 += 2.f * CEPS;
        float inv0 = 1.f / dv0, inv1 = 1.f / dv1;
        float* op0 = O_ + ((size_t)(bb * L_ + l0 + lb + qrow)) * D_ + hh * 64;
        float* op1 = op0 + 8 * D_;
#pragma unroll
        for (int ni = 0; ni < 5; ++ni)
            if (ni < nf) {
                int col = nb3 + ni * 8 + qcol * 2;
                if (col < 64) {
                    *reinterpret_cast<float2*>(op0 + col) =
                        make_float2(o[ni][0] * inv0, o[ni][1] * inv0);
                    *reinterpret_cast<float2*>(op1 + col) =
                        make_float2(o[ni][2] * inv1, o[ni][3] * inv1);
                }
            }
        __syncthreads();
    }
}

// ---------------------------------------------------------------------------
extern "C" void kernel_launch(void* const* d_in, const int* in_sizes, int n_in,
                              void* d_out, int out_size) {
    const float* q = (const float*)d_in[0];
    const float* k = (const float*)d_in[1];
    const float* v = (const float*)d_in[2];
    const float* w = (const float*)d_in[3];
    float* out = (float*)d_out;

    cudaFuncSetAttribute(favor_k, cudaFuncAttributeMaxDynamicSharedMemorySize, KFL * 4);
    cudaFuncSetAttribute(favor_q, cudaFuncAttributeMaxDynamicSharedMemorySize, QFL * 4);

    zero_kernel<<<512, 256>>>();
    min_kernel<<<1024, 256>>>(k);
    favor_k<<<dim3(64, 4), 256, KFL * 4>>>(k, v, w);
    favor_q<<<dim3(64, 4), 256, QFL * 4>>>(q, w, out);
}

// round 6
// speedup vs baseline: 1.4499x; 1.4499x over previous
#include <cuda_runtime.h>
#include <cstdint>

// FAVOR+ attention via mma.sync tf32. 512-thread CTAs (16 warps) for issue
// parallelism. B=4, L=4096, D=1024, H=16 x d=64, m=256.

namespace {
constexpr int L_ = 4096, D_ = 1024;
constexpr float SCALE = 0.17677669529663687f, SC2 = SCALE * SCALE;
constexpr float CEPS = 1e-4f, INVSQM = 0.0625f;
// favor_k smem (word offsets)
constexpr int KW = 0;          // W    [256 f][72]  (d perm)
constexpr int KX = 18432;      // K    [128 l][72]
constexpr int KVo = 27648;     // Vaug [72 d'][136] (l perm; row 64 = ones)
constexpr int KP = 37440;      // k'   [128 f][136] (l perm)
constexpr int KH = 54848;      // eb[128]
constexpr int KFL = 54976;     // 219904 B
// favor_q smem
constexpr int QW = 0;          // W    [256 f][72]
constexpr int QP = 18432;      // Q [64][72] -> q' [64][264] -> opart [64][76]
constexpr int QKV = 35328;     // KV^T [72 d'][264] (f perm)
constexpr int QDEN = 54336;    // den[64]
constexpr int QFL = 54400;     // 217600 B
}

__device__ float g_kv[64 * 256 * 72];   // [bh][f][d'(64=ksum)]
__device__ unsigned g_min_ss;

__device__ __forceinline__ int p8(int j) { return ((j & 3) * 2) | (j >> 2); }
__device__ __forceinline__ uint32_t cvt_tf32(float x) {
    uint32_t r;
    asm("cvt.rna.tf32.f32 %0, %1;" : "=r"(r) : "f"(x));
    return r;
}
__device__ __forceinline__ void mma8(float* c, const uint32_t* a, const uint32_t* b) {
    asm volatile(
        "mma.sync.aligned.m16n8k8.row.col.f32.tf32.tf32.f32 "
        "{%0,%1,%2,%3},{%4,%5,%6,%7},{%8,%9},{%0,%1,%2,%3};"
        : "+f"(c[0]), "+f"(c[1]), "+f"(c[2]), "+f"(c[3])
        : "r"(a[0]), "r"(a[1]), "r"(a[2]), "r"(a[3]), "r"(b[0]), "r"(b[1]));
}

// ---------------------------------------------------------------------------
__global__ void zero_kernel() {
    size_t tid = (size_t)blockIdx.x * blockDim.x + threadIdx.x;
    size_t stride = (size_t)gridDim.x * blockDim.x;
    constexpr size_t n = (size_t)64 * 256 * 72;
    for (size_t i = tid; i < n; i += stride) g_kv[i] = 0.f;
    if (tid == 0) g_min_ss = 0x7F800000u;
}

__global__ __launch_bounds__(256) void min_kernel(const float* __restrict__ Kp) {
    int t = threadIdx.x;
    float mn = 3.4028235e38f;
#pragma unroll
    for (int it = 0; it < 16; ++it) {
        size_t ch = (size_t)blockIdx.x * 256 + it * 16 + (t >> 4);
        float4 v4 = *reinterpret_cast<const float4*>(Kp + ch * 64 + (t & 15) * 4);
        float ss = v4.x * v4.x + v4.y * v4.y + v4.z * v4.z + v4.w * v4.w;
        ss += __shfl_xor_sync(~0u, ss, 8); ss += __shfl_xor_sync(~0u, ss, 4);
        ss += __shfl_xor_sync(~0u, ss, 2); ss += __shfl_xor_sync(~0u, ss, 1);
        mn = fminf(mn, ss);
    }
    mn = fminf(mn, __shfl_xor_sync(~0u, mn, 16));
    __shared__ float wmin[8];
    if ((t & 31) == 0) wmin[t >> 5] = mn;
    __syncthreads();
    if (t < 8) {
        float m2 = wmin[t];
        m2 = fminf(m2, __shfl_xor_sync(0xffu, m2, 4));
        m2 = fminf(m2, __shfl_xor_sync(0xffu, m2, 2));
        m2 = fminf(m2, __shfl_xor_sync(0xffu, m2, 1));
        if (t == 0) atomicMin(&g_min_ss, __float_as_uint(m2));
    }
}

// ---------------------------------------------------------------------------
__global__ __launch_bounds__(512, 1) void favor_k(
    const float* __restrict__ K_, const float* __restrict__ V_,
    const float* __restrict__ W_) {
    extern __shared__ float s[];
    uint32_t* su = reinterpret_cast<uint32_t*>(s);
    const int t = threadIdx.x, w = t >> 5;
    const int qrow = (t & 31) >> 2, qcol = t & 3;
    const int bh = blockIdx.x, bb = bh >> 4, hh = bh & 15;
#pragma unroll
    for (int i = 0; i < 8; ++i) {   // W -> tf32 bits, d-permuted
        int idx = t + i * 512, f = idx >> 4, c4 = idx & 15;
        float4 wv = *reinterpret_cast<const float4*>(W_ + f * 64 + c4 * 4);
        uint32_t* dst = su + KW + f * 72 + (c4 >> 1) * 8 + (c4 & 1);
        dst[0] = cvt_tf32(wv.x); dst[2] = cvt_tf32(wv.y);
        dst[4] = cvt_tf32(wv.z); dst[6] = cvt_tf32(wv.w);
    }
    if (t < 128) {
        const uint32_t one = cvt_tf32(1.f);
#pragma unroll
        for (int r = 64; r < 72; ++r) su[KVo + r * 136 + t] = (r == 64) ? one : 0u;
    }
    const float stab = -0.5f * SC2 * __uint_as_float(g_min_ss);
    float kvacc[2][9][4] = {};
    __syncthreads();
    const int mb = (w >> 2) * 32, nb = (w & 3) * 32;     // GEMM1: 4m x 4n
    const int g2 = w >> 3, fb = (w & 7) * 16;            // GEMM2: 2 k-groups x 8 f
    const int pr = p8(qrow);

    for (int ti = 0; ti < 8; ++ti) {
        const int l0 = ((int)blockIdx.y * 8 + ti) * 128;
#pragma unroll
        for (int i = 0; i < 4; ++i) {
            int idx = t + i * 512, l = idx >> 4, c4 = idx & 15;
            size_t off = ((size_t)(bb * L_ + l0 + l)) * D_ + hh * 64 + c4 * 4;
            float4 kk = *reinterpret_cast<const float4*>(K_ + off);
            uint32_t* dst = su + KX + l * 72 + (c4 >> 1) * 8 + (c4 & 1);
            dst[0] = cvt_tf32(kk.x); dst[2] = cvt_tf32(kk.y);
            dst[4] = cvt_tf32(kk.z); dst[6] = cvt_tf32(kk.w);
            float ss = kk.x * kk.x + kk.y * kk.y + kk.z * kk.z + kk.w * kk.w;
            ss += __shfl_xor_sync(~0u, ss, 1);
            ss += __shfl_xor_sync(~0u, ss, 2);
            ss += __shfl_xor_sync(~0u, ss, 4);
            ss += __shfl_xor_sync(~0u, ss, 8);
            if ((t & 15) == 0) s[KH + l] = fmaf(-0.5f * SC2, ss, -stab);
            float4 vv = *reinterpret_cast<const float4*>(V_ + off);
            int lp = (l & ~7) | p8(l & 7);
            int d0 = c4 * 4;
            su[KVo + (d0 + 0) * 136 + lp] = cvt_tf32(vv.x);
            su[KVo + (d0 + 1) * 136 + lp] = cvt_tf32(vv.y);
            su[KVo + (d0 + 2) * 136 + lp] = cvt_tf32(vv.z);
            su[KVo + (d0 + 3) * 136 + lp] = cvt_tf32(vv.w);
        }
        __syncthreads();

#pragma unroll
        for (int h = 0; h < 2; ++h) {
            // ---- GEMM1: S(32x32 per warp) = K x W^T, f-half h ----
            float c[2][4][4] = {};
#pragma unroll
            for (int ks = 0; ks < 8; ++ks) {
                uint32_t a[2][4];
#pragma unroll
                for (int mi = 0; mi < 2; ++mi) {
                    const uint32_t* ap = su + KX + (mb + mi * 16 + qrow) * 72 + ks * 8 + 2 * qcol;
                    uint2 lo = *reinterpret_cast<const uint2*>(ap);
                    uint2 hi = *reinterpret_cast<const uint2*>(ap + 8 * 72);
                    a[mi][0] = lo.x; a[mi][1] = hi.x; a[mi][2] = lo.y; a[mi][3] = hi.y;
                }
#pragma unroll
                for (int ni = 0; ni < 4; ++ni) {
                    const uint32_t* bp = su + KW + (h * 128 + nb + ni * 8 + qrow) * 72 + ks * 8 + 2 * qcol;
                    uint2 bv = *reinterpret_cast<const uint2*>(bp);
                    uint32_t b2[2] = {bv.x, bv.y};
                    mma8(c[0][ni], a[0], b2);
                    mma8(c[1][ni], a[1], b2);
                }
            }
            // ---- epilogue: k' -> KP[f][l-perm] ----
#pragma unroll
            for (int mi = 0; mi < 2; ++mi) {
                int r0 = mb + mi * 16 + qrow;
                float eb0 = s[KH + r0], eb1 = s[KH + r0 + 8];
                int colA = mb + mi * 16 + pr;
#pragma unroll
                for (int ni = 0; ni < 4; ++ni) {
                    int fh = nb + ni * 8 + qcol * 2;
                    su[KP + fh * 136 + colA] =
                        cvt_tf32(INVSQM * (__expf(fmaf(SCALE, c[mi][ni][0], eb0)) + CEPS));
                    su[KP + (fh + 1) * 136 + colA] =
                        cvt_tf32(INVSQM * (__expf(fmaf(SCALE, c[mi][ni][1], eb0)) + CEPS));
                    su[KP + fh * 136 + colA + 8] =
                        cvt_tf32(INVSQM * (__expf(fmaf(SCALE, c[mi][ni][2], eb1)) + CEPS));
                    su[KP + (fh + 1) * 136 + colA + 8] =
                        cvt_tf32(INVSQM * (__expf(fmaf(SCALE, c[mi][ni][3], eb1)) + CEPS));
                }
            }
            __syncthreads();
            // ---- GEMM2: KV[f,72] += k'^T x Vaug (k-group g2) ----
#pragma unroll
            for (int ks = 0; ks < 8; ++ks) {
                int kc = g2 * 64 + ks * 8 + 2 * qcol;
                const uint32_t* ap = su + KP + (fb + qrow) * 136 + kc;
                uint2 lo = *reinterpret_cast<const uint2*>(ap);
                uint2 hi = *reinterpret_cast<const uint2*>(ap + 8 * 136);
                uint32_t a2[4] = {lo.x, hi.x, lo.y, hi.y};
#pragma unroll
                for (int ni = 0; ni < 9; ++ni) {
                    const uint32_t* bp = su + KVo + (ni * 8 + qrow) * 136 + kc;
                    uint2 bv = *reinterpret_cast<const uint2*>(bp);
                    uint32_t b2[2] = {bv.x, bv.y};
                    mma8(kvacc[h][ni], a2, b2);
                }
            }
            __syncthreads();
        }
    }
    float* g = g_kv + (size_t)bh * 256 * 72;
#pragma unroll
    for (int h = 0; h < 2; ++h)
#pragma unroll
        for (int ni = 0; ni < 9; ++ni) {
            int f0 = h * 128 + fb + qrow, d0 = ni * 8 + qcol * 2;
            atomicAdd(g + f0 * 72 + d0, kvacc[h][ni][0]);
            atomicAdd(g + f0 * 72 + d0 + 1, kvacc[h][ni][1]);
            atomicAdd(g + (f0 + 8) * 72 + d0, kvacc[h][ni][2]);
            atomicAdd(g + (f0 + 8) * 72 + d0 + 1, kvacc[h][ni][3]);
        }
}

// ---------------------------------------------------------------------------
__global__ __launch_bounds__(512, 1) void favor_q(
    const float* __restrict__ Q_, const float* __restrict__ W_,
    float* __restrict__ O_) {
    extern __shared__ float s[];
    uint32_t* su = reinterpret_cast<uint32_t*>(s);
    const int t = threadIdx.x, w = t >> 5;
    const int qrow = (t & 31) >> 2, qcol = t & 3;
    const int bh = blockIdx.x, bb = bh >> 4, hh = bh & 15;
#pragma unroll
    for (int i = 0; i < 8; ++i) {
        int idx = t + i * 512, f = idx >> 4, c4 = idx & 15;
        float4 wv = *reinterpret_cast<const float4*>(W_ + f * 64 + c4 * 4);
        uint32_t* dst = su + QW + f * 72 + (c4 >> 1) * 8 + (c4 & 1);
        dst[0] = cvt_tf32(wv.x); dst[2] = cvt_tf32(wv.y);
        dst[4] = cvt_tf32(wv.z); dst[6] = cvt_tf32(wv.w);
    }
    {
        const float* g = g_kv + (size_t)bh * 256 * 72;
        for (int i = t; i < 256 * 72; i += 512) {
            int f = i / 72, d = i - f * 72;
            su[QKV + d * 264 + (f & ~7) + p8(f & 7)] = cvt_tf32(g[i]);
        }
    }
    __syncthreads();
    const int mb1 = (w >> 2) * 16, nb1 = (w & 3) * 64;   // GEMM1: 4m x 4n
    const int g3 = w >> 3, w3 = w & 7;                    // GEMM3: 2 k-groups
    const int lb = (w3 >> 1) * 16, nh = w3 & 1;
    const int nf = nh ? 4 : 5, nb3 = nh ? 40 : 0;
    const int pe = p8(qcol * 2), po = p8(qcol * 2 + 1);

    for (int ti = 0; ti < 16; ++ti) {
        const int l0 = ((int)blockIdx.y * 16 + ti) * 64;
#pragma unroll
        for (int i = 0; i < 2; ++i) {
            int idx = t + i * 512, l = idx >> 4, c4 = idx & 15;
            size_t off = ((size_t)(bb * L_ + l0 + l)) * D_ + hh * 64 + c4 * 4;
            float4 qq = *reinterpret_cast<const float4*>(Q_ + off);
            uint32_t* dst = su + QP + l * 72 + (c4 >> 1) * 8 + (c4 & 1);
            dst[0] = cvt_tf32(qq.x); dst[2] = cvt_tf32(qq.y);
            dst[4] = cvt_tf32(qq.z); dst[6] = cvt_tf32(qq.w);
        }
        __syncthreads();
        // ---- GEMM1: S(16x64 per warp) = Q x W^T ----
        float c[8][4] = {};
#pragma unroll
        for (int ks = 0; ks < 8; ++ks) {
            const uint32_t* ap = su + QP + (mb1 + qrow) * 72 + ks * 8 + 2 * qcol;
            uint2 lo = *reinterpret_cast<const uint2*>(ap);
            uint2 hi = *reinterpret_cast<const uint2*>(ap + 8 * 72);
            uint32_t a2[4] = {lo.x, hi.x, lo.y, hi.y};
#pragma unroll
            for (int ni = 0; ni < 8; ++ni) {
                const uint32_t* bp = su + QW + (nb1 + ni * 8 + qrow) * 72 + ks * 8 + 2 * qcol;
                uint2 bv = *reinterpret_cast<const uint2*>(bp);
                uint32_t b2[2] = {bv.x, bv.y};
                mma8(c[ni], a2, b2);
            }
        }
        __syncthreads();   // Q tile dead; q' overwrites region
        // ---- epilogue: q' -> QP[l][f-perm] ----
#pragma unroll
        for (int ni = 0; ni < 8; ++ni) {
            int fg = nb1 + ni * 8;
            int r0 = mb1 + qrow;
            su[QP + r0 * 264 + fg + pe] = cvt_tf32(INVSQM * (__expf(SCALE * c[ni][0]) + CEPS));
            su[QP + r0 * 264 + fg + po] = cvt_tf32(INVSQM * (__expf(SCALE * c[ni][1]) + CEPS));
            su[QP + (r0 + 8) * 264 + fg + pe] = cvt_tf32(INVSQM * (__expf(SCALE * c[ni][2]) + CEPS));
            su[QP + (r0 + 8) * 264 + fg + po] = cvt_tf32(INVSQM * (__expf(SCALE * c[ni][3]) + CEPS));
        }
        __syncthreads();
        // ---- GEMM3: out[64,72] = q' x KV^T (k-group g3) ----
        float o[5][4] = {};
#pragma unroll
        for (int ks = 0; ks < 16; ++ks) {
            int kc = g3 * 128 + ks * 8 + 2 * qcol;
            const uint32_t* ap = su + QP + (lb + qrow) * 264 + kc;
            uint2 lo = *reinterpret_cast<const uint2*>(ap);
            uint2 hi = *reinterpret_cast<const uint2*>(ap + 8 * 264);
            uint32_t a2[4] = {lo.x, hi.x, lo.y, hi.y};
#pragma unroll
            for (int ni = 0; ni < 5; ++ni)
                if (ni < nf) {
                    const uint32_t* bp = su + QKV + (nb3 + ni * 8 + qrow) * 264 + kc;
                    uint2 bv = *reinterpret_cast<const uint2*>(bp);
                    uint32_t b2[2] = {bv.x, bv.y};
                    mma8(o[ni], a2, b2);
                }
        }
        __syncthreads();   // q' dead; reuse QP as partial buffer [64][76]
        if (g3 == 1) {
#pragma unroll
            for (int ni = 0; ni < 5; ++ni)
                if (ni < nf) {
                    int col = nb3 + ni * 8 + qcol * 2, r0 = lb + qrow;
                    s[QP + r0 * 76 + col] = o[ni][0];
                    s[QP + r0 * 76 + col + 1] = o[ni][1];
                    s[QP + (r0 + 8) * 76 + col] = o[ni][2];
                    s[QP + (r0 + 8) * 76 + col + 1] = o[ni][3];
                }
        }
        __syncthreads();
        if (g3 == 0) {
#pragma unroll
            for (int ni = 0; ni < 5; ++ni)
                if (ni < nf) {
                    int col = nb3 + ni * 8 + qcol * 2, r0 = lb + qrow;
                    o[ni][0] += s[QP + r0 * 76 + col];
                    o[ni][1] += s[QP + r0 * 76 + col + 1];
                    o[ni][2] += s[QP + (r0 + 8) * 76 + col];
                    o[ni][3] += s[QP + (r0 + 8) * 76 + col + 1];
                }
            if (nh == 1 && qcol == 0) {
                s[QDEN + lb + qrow] = o[3][0];
                s[QDEN + lb + qrow + 8] = o[3][2];
            }
        }
        __syncthreads();
        if (g3 == 0) {
            float dv0 = s[QDEN + lb + qrow], dv1 = s[QDEN + lb + qrow + 8];
            if (fabsf(dv0) <= CEPS) dv0 += 2.f * CEPS;
            if (fabsf(dv1) <= CEPS) dv1 += 2.f * CEPS;
            float inv0 = 1.f / dv0, inv1 = 1.f / dv1;
            float* op0 = O_ + ((size_t)(bb * L_ + l0 + lb + qrow)) * D_ + hh * 64;
            float* op1 = op0 + 8 * D_;
#pragma unroll
            for (int ni = 0; ni < 5; ++ni)
                if (ni < nf) {
                    int col = nb3 + ni * 8 + qcol * 2;
                    if (col < 64) {
                        *reinterpret_cast<float2*>(op0 + col) =
                            make_float2(o[ni][0] * inv0, o[ni][1] * inv0);
                        *reinterpret_cast<float2*>(op1 + col) =
                            make_float2(o[ni][2] * inv1, o[ni][3] * inv1);
                    }
                }
        }
        __syncthreads();
    }
}

// ---------------------------------------------------------------------------
extern "C" void kernel_launch(void* const* d_in, const int* in_sizes, int n_in,
                              void* d_out, int out_size) {
    const float* q = (const float*)d_in[0];
    const float* k = (const float*)d_in[1];
    const float* v = (const float*)d_in[2];
    const float* w = (const float*)d_in[3];
    float* out = (float*)d_out;

    cudaFuncSetAttribute(favor_k, cudaFuncAttributeMaxDynamicSharedMemorySize, KFL * 4);
    cudaFuncSetAttribute(favor_q, cudaFuncAttributeMaxDynamicSharedMemorySize, QFL * 4);

    zero_kernel<<<512, 256>>>();
    min_kernel<<<1024, 256>>>(k);
    favor_k<<<dim3(64, 4), 512, KFL * 4>>>(k, v, w);
    favor_q<<<dim3(64, 4), 512, QFL * 4>>>(q, w, out);
}

// round 7
// speedup vs baseline: 1.6897x; 1.1654x over previous
#include <cuda_runtime.h>
#include <cstdint>

// FAVOR+ attention via mma.sync tf32. favor_q uses GEMM1-C -> GEMM3-A
// fragment reuse (q' never hits smem). B=4, L=4096, D=1024, H=16 x d=64, m=256.

namespace {
constexpr int L_ = 4096, D_ = 1024;
constexpr float SCALE = 0.17677669529663687f, SC2 = SCALE * SCALE;
constexpr float CEPS = 1e-4f, INVSQM = 0.0625f;
// favor_k smem (word offsets)
constexpr int KW = 0;          // W    [256 f][72]  (d perm)
constexpr int KX = 18432;      // K    [128 l][72]
constexpr int KVo = 27648;     // Vaug [72 d'][136] (l perm; row 64 = ones)
constexpr int KP = 37440;      // k'   [128 f][136] (l perm)
constexpr int KH = 54848;      // eb[128]
constexpr int KFL = 54976;     // 219904 B
// favor_q smem
constexpr int QW = 0;          // W    [256 f][72] (paired perm)
constexpr int QT = 18432;      // Q    [128 l][72] (paired perm)
constexpr int QKV = 27648;     // KV^T [72 d'][264] NATURAL f order
constexpr int QOP = 46656;     // out partials [128][72] fp32
constexpr int QFL = 55872;     // 223488 B
}

__device__ float g_kv[64 * 256 * 72];   // [bh][f][d'(64=ksum)]
__device__ unsigned g_min_ss;

__device__ __forceinline__ int p8(int j) { return ((j & 3) * 2) | (j >> 2); }
__device__ __forceinline__ uint32_t cvt_tf32(float x) {
    uint32_t r;
    asm("cvt.rna.tf32.f32 %0, %1;" : "=r"(r) : "f"(x));
    return r;
}
__device__ __forceinline__ void mma8(float* c, const uint32_t* a, const uint32_t* b) {
    asm volatile(
        "mma.sync.aligned.m16n8k8.row.col.f32.tf32.tf32.f32 "
        "{%0,%1,%2,%3},{%4,%5,%6,%7},{%8,%9},{%0,%1,%2,%3};"
        : "+f"(c[0]), "+f"(c[1]), "+f"(c[2]), "+f"(c[3])
        : "r"(a[0]), "r"(a[1]), "r"(a[2]), "r"(a[3]), "r"(b[0]), "r"(b[1]));
}

// ---------------------------------------------------------------------------
__global__ void zero_kernel() {
    size_t tid = (size_t)blockIdx.x * blockDim.x + threadIdx.x;
    size_t stride = (size_t)gridDim.x * blockDim.x;
    constexpr size_t n = (size_t)64 * 256 * 72;
    for (size_t i = tid; i < n; i += stride) g_kv[i] = 0.f;
    if (tid == 0) g_min_ss = 0x7F800000u;
}

__global__ __launch_bounds__(256) void min_kernel(const float* __restrict__ Kp) {
    int t = threadIdx.x;
    float mn = 3.4028235e38f;
#pragma unroll
    for (int it = 0; it < 16; ++it) {
        size_t ch = (size_t)blockIdx.x * 256 + it * 16 + (t >> 4);
        float4 v4 = *reinterpret_cast<const float4*>(Kp + ch * 64 + (t & 15) * 4);
        float ss = v4.x * v4.x + v4.y * v4.y + v4.z * v4.z + v4.w * v4.w;
        ss += __shfl_xor_sync(~0u, ss, 8); ss += __shfl_xor_sync(~0u, ss, 4);
        ss += __shfl_xor_sync(~0u, ss, 2); ss += __shfl_xor_sync(~0u, ss, 1);
        mn = fminf(mn, ss);
    }
    mn = fminf(mn, __shfl_xor_sync(~0u, mn, 16));
    __shared__ float wmin[8];
    if ((t & 31) == 0) wmin[t >> 5] = mn;
    __syncthreads();
    if (t < 8) {
        float m2 = wmin[t];
        m2 = fminf(m2, __shfl_xor_sync(0xffu, m2, 4));
        m2 = fminf(m2, __shfl_xor_sync(0xffu, m2, 2));
        m2 = fminf(m2, __shfl_xor_sync(0xffu, m2, 1));
        if (t == 0) atomicMin(&g_min_ss, __float_as_uint(m2));
    }
}

// ---------------------------------------------------------------------------
__global__ __launch_bounds__(512, 1) void favor_k(
    const float* __restrict__ K_, const float* __restrict__ V_,
    const float* __restrict__ W_) {
    extern __shared__ float s[];
    uint32_t* su = reinterpret_cast<uint32_t*>(s);
    const int t = threadIdx.x, w = t >> 5;
    const int qrow = (t & 31) >> 2, qcol = t & 3;
    const int bh = blockIdx.x, bb = bh >> 4, hh = bh & 15;
#pragma unroll
    for (int i = 0; i < 8; ++i) {
        int idx = t + i * 512, f = idx >> 4, c4 = idx & 15;
        float4 wv = *reinterpret_cast<const float4*>(W_ + f * 64 + c4 * 4);
        uint32_t* dst = su + KW + f * 72 + (c4 >> 1) * 8 + (c4 & 1);
        dst[0] = cvt_tf32(wv.x); dst[2] = cvt_tf32(wv.y);
        dst[4] = cvt_tf32(wv.z); dst[6] = cvt_tf32(wv.w);
    }
    if (t < 128) {
        const uint32_t one = cvt_tf32(1.f);
#pragma unroll
        for (int r = 64; r < 72; ++r) su[KVo + r * 136 + t] = (r == 64) ? one : 0u;
    }
    const float stab = -0.5f * SC2 * __uint_as_float(g_min_ss);
    float kvacc[2][9][4] = {};
    __syncthreads();
    const int mb = (w >> 2) * 32, nb = (w & 3) * 32;
    const int g2 = w >> 3, fb = (w & 7) * 16;
    const int pr = p8(qrow);

    for (int ti = 0; ti < 8; ++ti) {
        const int l0 = ((int)blockIdx.y * 8 + ti) * 128;
#pragma unroll
        for (int i = 0; i < 4; ++i) {
            int idx = t + i * 512, l = idx >> 4, c4 = idx & 15;
            size_t off = ((size_t)(bb * L_ + l0 + l)) * D_ + hh * 64 + c4 * 4;
            float4 kk = *reinterpret_cast<const float4*>(K_ + off);
            uint32_t* dst = su + KX + l * 72 + (c4 >> 1) * 8 + (c4 & 1);
            dst[0] = cvt_tf32(kk.x); dst[2] = cvt_tf32(kk.y);
            dst[4] = cvt_tf32(kk.z); dst[6] = cvt_tf32(kk.w);
            float ss = kk.x * kk.x + kk.y * kk.y + kk.z * kk.z + kk.w * kk.w;
            ss += __shfl_xor_sync(~0u, ss, 1);
            ss += __shfl_xor_sync(~0u, ss, 2);
            ss += __shfl_xor_sync(~0u, ss, 4);
            ss += __shfl_xor_sync(~0u, ss, 8);
            if ((t & 15) == 0) s[KH + l] = fmaf(-0.5f * SC2, ss, -stab);
            float4 vv = *reinterpret_cast<const float4*>(V_ + off);
            int lp = (l & ~7) | p8(l & 7);
            int d0 = c4 * 4;
            su[KVo + (d0 + 0) * 136 + lp] = cvt_tf32(vv.x);
            su[KVo + (d0 + 1) * 136 + lp] = cvt_tf32(vv.y);
            su[KVo + (d0 + 2) * 136 + lp] = cvt_tf32(vv.z);
            su[KVo + (d0 + 3) * 136 + lp] = cvt_tf32(vv.w);
        }
        __syncthreads();

#pragma unroll
        for (int h = 0; h < 2; ++h) {
            float c[2][4][4] = {};
#pragma unroll
            for (int ks = 0; ks < 8; ++ks) {
                uint32_t a[2][4];
#pragma unroll
                for (int mi = 0; mi < 2; ++mi) {
                    const uint32_t* ap = su + KX + (mb + mi * 16 + qrow) * 72 + ks * 8 + 2 * qcol;
                    uint2 lo = *reinterpret_cast<const uint2*>(ap);
                    uint2 hi = *reinterpret_cast<const uint2*>(ap + 8 * 72);
                    a[mi][0] = lo.x; a[mi][1] = hi.x; a[mi][2] = lo.y; a[mi][3] = hi.y;
                }
#pragma unroll
                for (int ni = 0; ni < 4; ++ni) {
                    const uint32_t* bp = su + KW + (h * 128 + nb + ni * 8 + qrow) * 72 + ks * 8 + 2 * qcol;
                    uint2 bv = *reinterpret_cast<const uint2*>(bp);
                    uint32_t b2[2] = {bv.x, bv.y};
                    mma8(c[0][ni], a[0], b2);
                    mma8(c[1][ni], a[1], b2);
                }
            }
#pragma unroll
            for (int mi = 0; mi < 2; ++mi) {
                int r0 = mb + mi * 16 + qrow;
                float eb0 = s[KH + r0], eb1 = s[KH + r0 + 8];
                int colA = mb + mi * 16 + pr;
#pragma unroll
                for (int ni = 0; ni < 4; ++ni) {
                    int fh = nb + ni * 8 + qcol * 2;
                    su[KP + fh * 136 + colA] =
                        cvt_tf32(INVSQM * (__expf(fmaf(SCALE, c[mi][ni][0], eb0)) + CEPS));
                    su[KP + (fh + 1) * 136 + colA] =
                        cvt_tf32(INVSQM * (__expf(fmaf(SCALE, c[mi][ni][1], eb0)) + CEPS));
                    su[KP + fh * 136 + colA + 8] =
                        cvt_tf32(INVSQM * (__expf(fmaf(SCALE, c[mi][ni][2], eb1)) + CEPS));
                    su[KP + (fh + 1) * 136 + colA + 8] =
                        cvt_tf32(INVSQM * (__expf(fmaf(SCALE, c[mi][ni][3], eb1)) + CEPS));
                }
            }
            __syncthreads();
#pragma unroll
            for (int ks = 0; ks < 8; ++ks) {
                int kc = g2 * 64 + ks * 8 + 2 * qcol;
                const uint32_t* ap = su + KP + (fb + qrow) * 136 + kc;
                uint2 lo = *reinterpret_cast<const uint2*>(ap);
                uint2 hi = *reinterpret_cast<const uint2*>(ap + 8 * 136);
                uint32_t a2[4] = {lo.x, hi.x, lo.y, hi.y};
#pragma unroll
                for (int ni = 0; ni < 9; ++ni) {
                    const uint32_t* bp = su + KVo + (ni * 8 + qrow) * 136 + kc;
                    uint2 bv = *reinterpret_cast<const uint2*>(bp);
                    uint32_t b2[2] = {bv.x, bv.y};
                    mma8(kvacc[h][ni], a2, b2);
                }
            }
            __syncthreads();
        }
    }
    float* g = g_kv + (size_t)bh * 256 * 72;
#pragma unroll
    for (int h = 0; h < 2; ++h)
#pragma unroll
        for (int ni = 0; ni < 9; ++ni) {
            int f0 = h * 128 + fb + qrow, d0 = ni * 8 + qcol * 2;
            atomicAdd(g + f0 * 72 + d0, kvacc[h][ni][0]);
            atomicAdd(g + f0 * 72 + d0 + 1, kvacc[h][ni][1]);
            atomicAdd(g + (f0 + 8) * 72 + d0, kvacc[h][ni][2]);
            atomicAdd(g + (f0 + 8) * 72 + d0 + 1, kvacc[h][ni][3]);
        }
}

// ---------------------------------------------------------------------------
// favor_q: 128-row tiles. 16 warps = 8 m-slots x 2 f-groups. GEMM1 C-frags
// become GEMM3 A-frags after exp (no q' smem round trip). KV^T stored in
// NATURAL f order so B uint2 supplies f={2qc,2qc+1} matching C cols.
// ---------------------------------------------------------------------------
__global__ __launch_bounds__(512, 1) void favor_q(
    const float* __restrict__ Q_, const float* __restrict__ W_,
    float* __restrict__ O_) {
    extern __shared__ float s[];
    uint32_t* su = reinterpret_cast<uint32_t*>(s);
    const int t = threadIdx.x, w = t >> 5, lane = t & 31;
    const int qrow = lane >> 2, qc = t & 3;
    const int bh = blockIdx.x, bb = bh >> 4, hh = bh & 15;
#pragma unroll
    for (int i = 0; i < 8; ++i) {
        int idx = t + i * 512, f = idx >> 4, c4 = idx & 15;
        float4 wv = *reinterpret_cast<const float4*>(W_ + f * 64 + c4 * 4);
        uint32_t* dst = su + QW + f * 72 + (c4 >> 1) * 8 + (c4 & 1);
        dst[0] = cvt_tf32(wv.x); dst[2] = cvt_tf32(wv.y);
        dst[4] = cvt_tf32(wv.z); dst[6] = cvt_tf32(wv.w);
    }
    {   // KV^T natural order: su[QKV + d*264 + f]
        const float* g = g_kv + (size_t)bh * 256 * 72;
        for (int i = t; i < 256 * 72; i += 512) {
            int f = i / 72, d = i - f * 72;
            su[QKV + d * 264 + f] = cvt_tf32(g[i]);
        }
    }
    __syncthreads();
    const int ms = (w & 7) * 16, fg = w >> 3;

    for (int ti = 0; ti < 8; ++ti) {
        const int l0 = ((int)blockIdx.y * 8 + ti) * 128;
#pragma unroll
        for (int i = 0; i < 4; ++i) {
            int idx = t + i * 512, l = idx >> 4, c4 = idx & 15;
            size_t off = ((size_t)(bb * L_ + l0 + l)) * D_ + hh * 64 + c4 * 4;
            float4 qq = *reinterpret_cast<const float4*>(Q_ + off);
            uint32_t* dst = su + QT + l * 72 + (c4 >> 1) * 8 + (c4 & 1);
            dst[0] = cvt_tf32(qq.x); dst[2] = cvt_tf32(qq.y);
            dst[4] = cvt_tf32(qq.z); dst[6] = cvt_tf32(qq.w);
        }
        __syncthreads();
        // ---- GEMM1: S(16m x 128n per warp) = Q x W^T, n-range = fg*128 ----
        float c[16][4] = {};
#pragma unroll
        for (int ks = 0; ks < 8; ++ks) {
            const uint32_t* ap = su + QT + (ms + qrow) * 72 + ks * 8 + 2 * qc;
            uint2 lo = *reinterpret_cast<const uint2*>(ap);
            uint2 hi = *reinterpret_cast<const uint2*>(ap + 8 * 72);
            uint32_t a2[4] = {lo.x, hi.x, lo.y, hi.y};
#pragma unroll
            for (int ni = 0; ni < 16; ++ni) {
                const uint32_t* bp = su + QW + (fg * 128 + ni * 8 + qrow) * 72 + ks * 8 + 2 * qc;
                uint2 bv = *reinterpret_cast<const uint2*>(bp);
                uint32_t b2[2] = {bv.x, bv.y};
                mma8(c[ni], a2, b2);
            }
        }
        // ---- epilogue in registers: C -> tf32 A-frags (slot swap 1<->2) ----
        uint32_t (*cu)[4] = reinterpret_cast<uint32_t(*)[4]>(c);
#pragma unroll
        for (int ni = 0; ni < 16; ++ni) {
            float v0 = INVSQM * (__expf(SCALE * c[ni][0]) + CEPS);
            float v1 = INVSQM * (__expf(SCALE * c[ni][1]) + CEPS);
            float v2 = INVSQM * (__expf(SCALE * c[ni][2]) + CEPS);
            float v3 = INVSQM * (__expf(SCALE * c[ni][3]) + CEPS);
            cu[ni][0] = cvt_tf32(v0); cu[ni][1] = cvt_tf32(v2);
            cu[ni][2] = cvt_tf32(v1); cu[ni][3] = cvt_tf32(v3);
        }
        // ---- GEMM3: out[16m x 72n] partial over k-range fg*128 ----
        float o[9][4] = {};
#pragma unroll
        for (int j = 0; j < 16; ++j) {
#pragma unroll
            for (int ni = 0; ni < 9; ++ni) {
                const uint32_t* bp = su + QKV + (ni * 8 + qrow) * 264 + fg * 128 + j * 8 + 2 * qc;
                uint2 bv = *reinterpret_cast<const uint2*>(bp);
                uint32_t b2[2] = {bv.x, bv.y};
                mma8(o[ni], cu[j], b2);
            }
        }
        __syncthreads();
        if (fg == 1) {   // dump partials
            int r0 = ms + qrow;
#pragma unroll
            for (int ni = 0; ni < 9; ++ni) {
                int col = ni * 8 + 2 * qc;
                *reinterpret_cast<float2*>(s + QOP + r0 * 72 + col) =
                    make_float2(o[ni][0], o[ni][1]);
                *reinterpret_cast<float2*>(s + QOP + (r0 + 8) * 72 + col) =
                    make_float2(o[ni][2], o[ni][3]);
            }
        }
        __syncthreads();
        if (fg == 0) {   // reduce, divide, store
            int r0 = ms + qrow;
#pragma unroll
            for (int ni = 0; ni < 9; ++ni) {
                int col = ni * 8 + 2 * qc;
                float2 p0 = *reinterpret_cast<const float2*>(s + QOP + r0 * 72 + col);
                float2 p1 = *reinterpret_cast<const float2*>(s + QOP + (r0 + 8) * 72 + col);
                o[ni][0] += p0.x; o[ni][1] += p0.y;
                o[ni][2] += p1.x; o[ni][3] += p1.y;
            }
            float den0 = __shfl_sync(~0u, o[8][0], lane & ~3);
            float den1 = __shfl_sync(~0u, o[8][2], lane & ~3);
            if (fabsf(den0) <= CEPS) den0 += 2.f * CEPS;
            if (fabsf(den1) <= CEPS) den1 += 2.f * CEPS;
            float inv0 = 1.f / den0, inv1 = 1.f / den1;
            float* op0 = O_ + ((size_t)(bb * L_ + l0 + r0)) * D_ + hh * 64;
            float* op1 = op0 + 8 * D_;
#pragma unroll
            for (int ni = 0; ni < 8; ++ni) {
                int col = ni * 8 + 2 * qc;
                *reinterpret_cast<float2*>(op0 + col) =
                    make_float2(o[ni][0] * inv0, o[ni][1] * inv0);
                *reinterpret_cast<float2*>(op1 + col) =
                    make_float2(o[ni][2] * inv1, o[ni][3] * inv1);
            }
        }
    }
}

// ---------------------------------------------------------------------------
extern "C" void kernel_launch(void* const* d_in, const int* in_sizes, int n_in,
                              void* d_out, int out_size) {
    const float* q = (const float*)d_in[0];
    const float* k = (const float*)d_in[1];
    const float* v = (const float*)d_in[2];
    const float* w = (const float*)d_in[3];
    float* out = (float*)d_out;

    cudaFuncSetAttribute(favor_k, cudaFuncAttributeMaxDynamicSharedMemorySize, KFL * 4);
    cudaFuncSetAttribute(favor_q, cudaFuncAttributeMaxDynamicSharedMemorySize, QFL * 4);

    zero_kernel<<<512, 256>>>();
    min_kernel<<<1024, 256>>>(k);
    favor_k<<<dim3(64, 4), 512, KFL * 4>>>(k, v, w);
    favor_q<<<dim3(64, 4), 512, QFL * 4>>>(q, w, out);
}

// round 10
// speedup vs baseline: 2.3729x; 1.4043x over previous
#include <cuda_runtime.h>
#include <cuda_fp16.h>
#include <cstdint>

// FAVOR+ attention via mma.sync m16n8k16 fp16 (fp32 accum).
// B=4, L=4096, D=1024, H=16 x d=64, m=256.

namespace {
constexpr int L_ = 4096, D_ = 1024;
constexpr float SCALE = 0.17677669529663687f, SC2 = SCALE * SCALE;
constexpr float CEPS = 1e-4f, INVSQM = 0.0625f;
// favor_k smem (uint32 word offsets); all strides == 8 (mod 32)
constexpr int KW = 0;          // W    [256 f][40]  (32 half2 + pad)
constexpr int KX = 10240;      // K    [128 l][40]
constexpr int KVo = 15360;     // Vaug [72 d'][72]  (64 half2 l + pad; row 64 = ones)
constexpr int KP = 20544;      // k'   [128 f][72]  (64 half2 l)
constexpr int KH = 29760;      // eb[128] fp32
constexpr int KFL = 29888;     // 119552 B
// favor_q smem
constexpr int QW = 0;          // W    [256 f][40]
constexpr int QT = 10240;      // Q    [128 l][40]
constexpr int QKV = 15360;     // KV^T [72 d'][136] (128 half2 f)
constexpr int QOP = 25152;     // out partials [128][72] fp32
constexpr int QFL = 34368;     // 137472 B
}

__device__ float g_kv[64 * 256 * 72];   // [bh][f][d'(64=ksum)]
__device__ unsigned g_min_ss;

__device__ __forceinline__ int p8(int j) { return ((j & 3) * 2) | (j >> 2); }
__device__ __forceinline__ int pp(int j) { return (j & ~7) | p8(j & 7); }   // half2-idx perm
__device__ __forceinline__ uint32_t h2(float a, float b) {
    __half2 h = __floats2half2_rn(a, b);
    return *reinterpret_cast<uint32_t*>(&h);
}
__device__ __forceinline__ void mma16(float* c, const uint32_t* a, const uint32_t* b) {
    asm volatile(
        "mma.sync.aligned.m16n8k16.row.col.f32.f16.f16.f32 "
        "{%0,%1,%2,%3},{%4,%5,%6,%7},{%8,%9},{%0,%1,%2,%3};"
        : "+f"(c[0]), "+f"(c[1]), "+f"(c[2]), "+f"(c[3])
        : "r"(a[0]), "r"(a[1]), "r"(a[2]), "r"(a[3]), "r"(b[0]), "r"(b[1]));
}

// ---------------------------------------------------------------------------
__global__ void zero_kernel() {
    size_t tid = (size_t)blockIdx.x * blockDim.x + threadIdx.x;
    size_t stride = (size_t)gridDim.x * blockDim.x;
    constexpr size_t n = (size_t)64 * 256 * 72;
    for (size_t i = tid; i < n; i += stride) g_kv[i] = 0.f;
    if (tid == 0) g_min_ss = 0x7F800000u;
}

__global__ __launch_bounds__(256) void min_kernel(const float* __restrict__ Kp) {
    int t = threadIdx.x;
    float mn = 3.4028235e38f;
#pragma unroll
    for (int it = 0; it < 16; ++it) {
        size_t ch = (size_t)blockIdx.x * 256 + it * 16 + (t >> 4);
        float4 v4 = *reinterpret_cast<const float4*>(Kp + ch * 64 + (t & 15) * 4);
        float ss = v4.x * v4.x + v4.y * v4.y + v4.z * v4.z + v4.w * v4.w;
        ss += __shfl_xor_sync(~0u, ss, 8); ss += __shfl_xor_sync(~0u, ss, 4);
        ss += __shfl_xor_sync(~0u, ss, 2); ss += __shfl_xor_sync(~0u, ss, 1);
        mn = fminf(mn, ss);
    }
    mn = fminf(mn, __shfl_xor_sync(~0u, mn, 16));
    __shared__ float wmin[8];
    if ((t & 31) == 0) wmin[t >> 5] = mn;
    __syncthreads();
    if (t < 8) {
        float m2 = wmin[t];
        m2 = fminf(m2, __shfl_xor_sync(0xffu, m2, 4));
        m2 = fminf(m2, __shfl_xor_sync(0xffu, m2, 2));
        m2 = fminf(m2, __shfl_xor_sync(0xffu, m2, 1));
        if (t == 0) atomicMin(&g_min_ss, __float_as_uint(m2));
    }
}

// ---------------------------------------------------------------------------
__global__ __launch_bounds__(512, 1) void favor_k(
    const float* __restrict__ K_, const float* __restrict__ V_,
    const float* __restrict__ W_) {
    extern __shared__ float s[];
    uint32_t* su = reinterpret_cast<uint32_t*>(s);
    __half* sh16 = reinterpret_cast<__half*>(s);
    const int t = threadIdx.x, w = t >> 5;
    const int qrow = (t & 31) >> 2, qc = t & 3;
    const int bh = blockIdx.x, bb = bh >> 4, hh = bh & 15;
#pragma unroll
    for (int i = 0; i < 8; ++i) {   // W -> fp16 half2, paired perm
        int idx = t + i * 512, f = idx >> 4, c4 = idx & 15;
        float4 wv = *reinterpret_cast<const float4*>(W_ + f * 64 + c4 * 4);
        su[KW + f * 40 + pp(2 * c4)] = h2(wv.x, wv.y);
        su[KW + f * 40 + pp(2 * c4 + 1)] = h2(wv.z, wv.w);
    }
    {   // Vaug pad rows (row 64 = ones)
        int r = 64 + (t >> 6), c = t & 63;
        su[KVo + r * 72 + c] = (r == 64) ? h2(1.f, 1.f) : 0u;
    }
    const float stab = -0.5f * SC2 * __uint_as_float(g_min_ss);
    float kvacc[2][9][4] = {};
    __syncthreads();
    const int mb = (w >> 2) * 32, nb = (w & 3) * 32;   // GEMM1: 4m x 4n
    const int g2 = w >> 3, fb = (w & 7) * 16;          // GEMM2: 2 k-grp x 8 f

    for (int ti = 0; ti < 8; ++ti) {
        const int l0 = ((int)blockIdx.y * 8 + ti) * 128;
#pragma unroll
        for (int i = 0; i < 4; ++i) {
            int idx = t + i * 512, l = idx >> 4, c4 = idx & 15;
            size_t off = ((size_t)(bb * L_ + l0 + l)) * D_ + hh * 64 + c4 * 4;
            float4 kk = *reinterpret_cast<const float4*>(K_ + off);
            su[KX + l * 40 + pp(2 * c4)] = h2(kk.x, kk.y);
            su[KX + l * 40 + pp(2 * c4 + 1)] = h2(kk.z, kk.w);
            float ss = kk.x * kk.x + kk.y * kk.y + kk.z * kk.z + kk.w * kk.w;
            ss += __shfl_xor_sync(~0u, ss, 1);
            ss += __shfl_xor_sync(~0u, ss, 2);
            ss += __shfl_xor_sync(~0u, ss, 4);
            ss += __shfl_xor_sync(~0u, ss, 8);
            if ((t & 15) == 0) s[KH + l] = fmaf(-0.5f * SC2, ss, -stab);
            float4 vv = *reinterpret_cast<const float4*>(V_ + off);
            int hp = pp(l >> 1) * 2 + (l & 1);   // half-position of l
            int d0 = c4 * 4;
            sh16[(KVo + (d0 + 0) * 72) * 2 + hp] = __float2half(vv.x);
            sh16[(KVo + (d0 + 1) * 72) * 2 + hp] = __float2half(vv.y);
            sh16[(KVo + (d0 + 2) * 72) * 2 + hp] = __float2half(vv.z);
            sh16[(KVo + (d0 + 3) * 72) * 2 + hp] = __float2half(vv.w);
        }
        __syncthreads();

#pragma unroll
        for (int h = 0; h < 2; ++h) {
            // ---- GEMM1: S(32x32 per warp) = K x W^T, f-half h (k=64 -> 4 ks)
            float c[2][4][4] = {};
#pragma unroll
            for (int ks = 0; ks < 4; ++ks) {
                uint32_t a[2][4];
#pragma unroll
                for (int mi = 0; mi < 2; ++mi) {
                    const uint32_t* ap = su + KX + (mb + mi * 16 + qrow) * 40 + ks * 8 + 2 * qc;
                    uint2 lo = *reinterpret_cast<const uint2*>(ap);
                    uint2 hi = *reinterpret_cast<const uint2*>(ap + 8 * 40);
                    a[mi][0] = lo.x; a[mi][1] = hi.x; a[mi][2] = lo.y; a[mi][3] = hi.y;
                }
#pragma unroll
                for (int ni = 0; ni < 4; ++ni) {
                    const uint32_t* bp = su + KW + (h * 128 + nb + ni * 8 + qrow) * 40 + ks * 8 + 2 * qc;
                    uint2 bv = *reinterpret_cast<const uint2*>(bp);
                    uint32_t b2[2] = {bv.x, bv.y};
                    mma16(c[0][ni], a[0], b2);
                    mma16(c[1][ni], a[1], b2);
                }
            }
            // ---- epilogue: k' -> KP[f][l] fp16 (transposed scatter) ----
#pragma unroll
            for (int mi = 0; mi < 2; ++mi) {
                int r0 = mb + mi * 16 + qrow;
                float eb0 = s[KH + r0], eb1 = s[KH + r0 + 8];
                int hp0 = pp(r0 >> 1) * 2 + (r0 & 1);
                int hp1 = pp((r0 + 8) >> 1) * 2 + (r0 & 1);
#pragma unroll
                for (int ni = 0; ni < 4; ++ni) {
                    int fh = nb + ni * 8 + qc * 2;
                    sh16[(KP + fh * 72) * 2 + hp0] =
                        __float2half(INVSQM * (__expf(fmaf(SCALE, c[mi][ni][0], eb0)) + CEPS));
                    sh16[(KP + (fh + 1) * 72) * 2 + hp0] =
                        __float2half(INVSQM * (__expf(fmaf(SCALE, c[mi][ni][1], eb0)) + CEPS));
                    sh16[(KP + fh * 72) * 2 + hp1] =
                        __float2half(INVSQM * (__expf(fmaf(SCALE, c[mi][ni][2], eb1)) + CEPS));
                    sh16[(KP + (fh + 1) * 72) * 2 + hp1] =
                        __float2half(INVSQM * (__expf(fmaf(SCALE, c[mi][ni][3], eb1)) + CEPS));
                }
            }
            __syncthreads();
            // ---- GEMM2: KV[f,72] += k'^T x Vaug (k=128 -> 8 chunks, split 2)
#pragma unroll
            for (int ks = 0; ks < 4; ++ks) {
                int kc = (g2 * 4 + ks) * 8 + 2 * qc;
                const uint32_t* ap = su + KP + (fb + qrow) * 72 + kc;
                uint2 lo = *reinterpret_cast<const uint2*>(ap);
                uint2 hi = *reinterpret_cast<const uint2*>(ap + 8 * 72);
                uint32_t a2[4] = {lo.x, hi.x, lo.y, hi.y};
#pragma unroll
                for (int ni = 0; ni < 9; ++ni) {
                    const uint32_t* bp = su + KVo + (ni * 8 + qrow) * 72 + kc;
                    uint2 bv = *reinterpret_cast<const uint2*>(bp);
                    uint32_t b2[2] = {bv.x, bv.y};
                    mma16(kvacc[h][ni], a2, b2);
                }
            }
            __syncthreads();
        }
    }
    float* g = g_kv + (size_t)bh * 256 * 72;
#pragma unroll
    for (int h = 0; h < 2; ++h)
#pragma unroll
        for (int ni = 0; ni < 9; ++ni) {
            int f0 = h * 128 + fb + qrow, d0 = ni * 8 + qc * 2;
            atomicAdd(g + f0 * 72 + d0, kvacc[h][ni][0]);
            atomicAdd(g + f0 * 72 + d0 + 1, kvacc[h][ni][1]);
            atomicAdd(g + (f0 + 8) * 72 + d0, kvacc[h][ni][2]);
            atomicAdd(g + (f0 + 8) * 72 + d0 + 1, kvacc[h][ni][3]);
        }
}

// ---------------------------------------------------------------------------
// favor_q: GEMM1 C-frags -> fp16 A-frags in registers (q' never in smem).
// ---------------------------------------------------------------------------
__global__ __launch_bounds__(512, 1) void favor_q(
    const float* __restrict__ Q_, const float* __restrict__ W_,
    float* __restrict__ O_) {
    extern __shared__ float s[];
    uint32_t* su = reinterpret_cast<uint32_t*>(s);
    __half* sh16 = reinterpret_cast<__half*>(s);
    const int t = threadIdx.x, w = t >> 5, lane = t & 31;
    const int qrow = lane >> 2, qc = t & 3;
    const int bh = blockIdx.x, bb = bh >> 4, hh = bh & 15;
#pragma unroll
    for (int i = 0; i < 8; ++i) {
        int idx = t + i * 512, f = idx >> 4, c4 = idx & 15;
        float4 wv = *reinterpret_cast<const float4*>(W_ + f * 64 + c4 * 4);
        su[QW + f * 40 + pp(2 * c4)] = h2(wv.x, wv.y);
        su[QW + f * 40 + pp(2 * c4 + 1)] = h2(wv.z, wv.w);
    }
    {   // KV^T [d][f] fp16, paired perm on f half2-idx
        const float* g = g_kv + (size_t)bh * 256 * 72;
        for (int i = t; i < 256 * 72; i += 512) {
            int f = i / 72, d = i - f * 72;
            sh16[(QKV + d * 136 + pp(f >> 1)) * 2 + (f & 1)] = __float2half(g[i]);
        }
    }
    __syncthreads();
    const int ms = (w & 7) * 16, fg = w >> 3;

    for (int ti = 0; ti < 8; ++ti) {
        const int l0 = ((int)blockIdx.y * 8 + ti) * 128;
#pragma unroll
        for (int i = 0; i < 4; ++i) {
            int idx = t + i * 512, l = idx >> 4, c4 = idx & 15;
            size_t off = ((size_t)(bb * L_ + l0 + l)) * D_ + hh * 64 + c4 * 4;
            float4 qq = *reinterpret_cast<const float4*>(Q_ + off);
            su[QT + l * 40 + pp(2 * c4)] = h2(qq.x, qq.y);
            su[QT + l * 40 + pp(2 * c4 + 1)] = h2(qq.z, qq.w);
        }
        __syncthreads();
        // ---- GEMM1: S(16m x 128n per warp), n-range fg*128, k=64 (4 ks) ----
        float c[16][4] = {};
#pragma unroll
        for (int ks = 0; ks < 4; ++ks) {
            const uint32_t* ap = su + QT + (ms + qrow) * 40 + ks * 8 + 2 * qc;
            uint2 lo = *reinterpret_cast<const uint2*>(ap);
            uint2 hi = *reinterpret_cast<const uint2*>(ap + 8 * 40);
            uint32_t a2[4] = {lo.x, hi.x, lo.y, hi.y};
#pragma unroll
            for (int ni = 0; ni < 16; ++ni) {
                const uint32_t* bp = su + QW + (fg * 128 + ni * 8 + qrow) * 40 + ks * 8 + 2 * qc;
                uint2 bv = *reinterpret_cast<const uint2*>(bp);
                uint32_t b2[2] = {bv.x, bv.y};
                mma16(c[ni], a2, b2);
            }
        }
        // ---- epilogue: exp + pack C pairs -> fp16 A-frags (k=16 each) ----
        uint32_t cu[8][4];
#pragma unroll
        for (int j = 0; j < 8; ++j) {
            float v00 = INVSQM * (__expf(SCALE * c[2 * j][0]) + CEPS);
            float v01 = INVSQM * (__expf(SCALE * c[2 * j][1]) + CEPS);
            float v02 = INVSQM * (__expf(SCALE * c[2 * j][2]) + CEPS);
            float v03 = INVSQM * (__expf(SCALE * c[2 * j][3]) + CEPS);
            float v10 = INVSQM * (__expf(SCALE * c[2 * j + 1][0]) + CEPS);
            float v11 = INVSQM * (__expf(SCALE * c[2 * j + 1][1]) + CEPS);
            float v12 = INVSQM * (__expf(SCALE * c[2 * j + 1][2]) + CEPS);
            float v13 = INVSQM * (__expf(SCALE * c[2 * j + 1][3]) + CEPS);
            cu[j][0] = h2(v00, v01);   // row qrow,  k 2qc,2qc+1
            cu[j][1] = h2(v02, v03);   // row qrow+8
            cu[j][2] = h2(v10, v11);   // row qrow,  k 2qc+8
            cu[j][3] = h2(v12, v13);   // row qrow+8
        }
        // ---- GEMM3: out[16m x 72] partial over f-range fg*128 (8 chunks) ----
        float o[9][4] = {};
#pragma unroll
        for (int j = 0; j < 8; ++j) {
#pragma unroll
            for (int ni = 0; ni < 9; ++ni) {
                const uint32_t* bp = su + QKV + (ni * 8 + qrow) * 136 + fg * 64 + j * 8 + 2 * qc;
                uint2 bv = *reinterpret_cast<const uint2*>(bp);
                uint32_t b2[2] = {bv.x, bv.y};
                mma16(o[ni], cu[j], b2);
            }
        }
        __syncthreads();
        if (fg == 1) {
            int r0 = ms + qrow;
#pragma unroll
            for (int ni = 0; ni < 9; ++ni) {
                int col = ni * 8 + 2 * qc;
                *reinterpret_cast<float2*>(s + QOP + r0 * 72 + col) =
                    make_float2(o[ni][0], o[ni][1]);
                *reinterpret_cast<float2*>(s + QOP + (r0 + 8) * 72 + col) =
                    make_float2(o[ni][2], o[ni][3]);
            }
        }
        __syncthreads();
        if (fg == 0) {
            int r0 = ms + qrow;
#pragma unroll
            for (int ni = 0; ni < 9; ++ni) {
                int col = ni * 8 + 2 * qc;
                float2 p0 = *reinterpret_cast<const float2*>(s + QOP + r0 * 72 + col);
                float2 p1 = *reinterpret_cast<const float2*>(s + QOP + (r0 + 8) * 72 + col);
                o[ni][0] += p0.x; o[ni][1] += p0.y;
                o[ni][2] += p1.x; o[ni][3] += p1.y;
            }
            float den0 = __shfl_sync(~0u, o[8][0], lane & ~3);
            float den1 = __shfl_sync(~0u, o[8][2], lane & ~3);
            if (fabsf(den0) <= CEPS) den0 += 2.f * CEPS;
            if (fabsf(den1) <= CEPS) den1 += 2.f * CEPS;
            float inv0 = 1.f / den0, inv1 = 1.f / den1;
            float* op0 = O_ + ((size_t)(bb * L_ + l0 + r0)) * D_ + hh * 64;
            float* op1 = op0 + 8 * D_;
#pragma unroll
            for (int ni = 0; ni < 8; ++ni) {
                int col = ni * 8 + 2 * qc;
                *reinterpret_cast<float2*>(op0 + col) =
                    make_float2(o[ni][0] * inv0, o[ni][1] * inv0);
                *reinterpret_cast<float2*>(op1 + col) =
                    make_float2(o[ni][2] * inv1, o[ni][3] * inv1);
            }
        }
    }
}

// ---------------------------------------------------------------------------
extern "C" void kernel_launch(void* const* d_in, const int* in_sizes, int n_in,
                              void* d_out, int out_size) {
    const float* q = (const float*)d_in[0];
    const float* k = (const float*)d_in[1];
    const float* v = (const float*)d_in[2];
    const float* w = (const float*)d_in[3];
    float* out = (float*)d_out;

    cudaFuncSetAttribute(favor_k, cudaFuncAttributeMaxDynamicSharedMemorySize, KFL * 4);
    cudaFuncSetAttribute(favor_q, cudaFuncAttributeMaxDynamicSharedMemorySize, QFL * 4);

    zero_kernel<<<512, 256>>>();
    min_kernel<<<1024, 256>>>(k);
    favor_k<<<dim3(64, 4), 512, KFL * 4>>>(k, v, w);
    favor_q<<<dim3(64, 4), 512, QFL * 4>>>(q, w, out);
}

// round 11
// speedup vs baseline: 2.5116x; 1.0585x over previous
#include <cuda_runtime.h>
#include <cuda_fp16.h>
#include <cstdint>

// FAVOR+ attention via mma.sync m16n8k16 fp16 (fp32 accum).
// 256-thread CTAs, 2 CTAs/SM co-residency. B=4, L=4096, D=1024, H=16 x d=64, m=256.

namespace {
constexpr int L_ = 4096, D_ = 1024;
constexpr float SCALE = 0.17677669529663687f, SC2 = SCALE * SCALE;
constexpr float CEPS = 1e-4f, INVSQM = 0.0625f;
// favor_k smem (uint32 word offsets)
constexpr int KW = 0;          // W    [256 f][40]  (32 half2 + pad)
constexpr int KX = 10240;      // K    [64 l][40]
constexpr int KVo = 12800;     // Vaug [72 d'][36]  (32 half2 l + pad; row 64 = ones)
constexpr int KP = 15392;      // k'   [128 f][36]  (32 half2 l)
constexpr int KH = 20000;      // eb[64] fp32
constexpr int KFL = 20064;     // 80256 B  (x2 CTA = 160.5 KB)
// favor_q smem
constexpr int QW = 0;          // W    [256 f][40]
constexpr int QT = 10240;      // Q    [64 l][40]
constexpr int QKV = 12800;     // KV^T [72 d'][136] (128 half2 f)
constexpr int QOP = 22592;     // out partials [64][72] fp32
constexpr int QFL = 27200;     // 108800 B (x2 CTA = 217.6 KB)
}

__device__ float g_kv[64 * 256 * 72];   // [bh][f][d'(64=ksum)]
__device__ unsigned g_min_ss;

__device__ __forceinline__ int p8(int j) { return ((j & 3) * 2) | (j >> 2); }
__device__ __forceinline__ int pp(int j) { return (j & ~7) | p8(j & 7); }   // half2-idx perm
__device__ __forceinline__ uint32_t h2(float a, float b) {
    __half2 h = __floats2half2_rn(a, b);
    return *reinterpret_cast<uint32_t*>(&h);
}
__device__ __forceinline__ void mma16(float* c, const uint32_t* a, const uint32_t* b) {
    asm volatile(
        "mma.sync.aligned.m16n8k16.row.col.f32.f16.f16.f32 "
        "{%0,%1,%2,%3},{%4,%5,%6,%7},{%8,%9},{%0,%1,%2,%3};"
        : "+f"(c[0]), "+f"(c[1]), "+f"(c[2]), "+f"(c[3])
        : "r"(a[0]), "r"(a[1]), "r"(a[2]), "r"(a[3]), "r"(b[0]), "r"(b[1]));
}

// ---------------------------------------------------------------------------
__global__ void init_kernel() { g_min_ss = 0x7F800000u; }

// min over ||k_row||^2 + zero g_kv (fused; both must precede favor_k)
__global__ __launch_bounds__(256) void min_kernel(const float* __restrict__ Kp) {
    int t = threadIdx.x;
    {   // zero scratch
        size_t tid = (size_t)blockIdx.x * 256 + t;
        constexpr size_t n = (size_t)64 * 256 * 72;
        for (size_t i = tid; i < n; i += (size_t)gridDim.x * 256) g_kv[i] = 0.f;
    }
    float mn = 3.4028235e38f;
#pragma unroll
    for (int it = 0; it < 16; ++it) {
        size_t ch = (size_t)blockIdx.x * 256 + it * 16 + (t >> 4);
        float4 v4 = *reinterpret_cast<const float4*>(Kp + ch * 64 + (t & 15) * 4);
        float ss = v4.x * v4.x + v4.y * v4.y + v4.z * v4.z + v4.w * v4.w;
        ss += __shfl_xor_sync(~0u, ss, 8); ss += __shfl_xor_sync(~0u, ss, 4);
        ss += __shfl_xor_sync(~0u, ss, 2); ss += __shfl_xor_sync(~0u, ss, 1);
        mn = fminf(mn, ss);
    }
    mn = fminf(mn, __shfl_xor_sync(~0u, mn, 16));
    __shared__ float wmin[8];
    if ((t & 31) == 0) wmin[t >> 5] = mn;
    __syncthreads();
    if (t < 8) {
        float m2 = wmin[t];
        m2 = fminf(m2, __shfl_xor_sync(0xffu, m2, 4));
        m2 = fminf(m2, __shfl_xor_sync(0xffu, m2, 2));
        m2 = fminf(m2, __shfl_xor_sync(0xffu, m2, 1));
        if (t == 0) atomicMin(&g_min_ss, __float_as_uint(m2));
    }
}

// ---------------------------------------------------------------------------
__global__ __launch_bounds__(256, 2) void favor_k(
    const float* __restrict__ K_, const float* __restrict__ V_,
    const float* __restrict__ W_) {
    extern __shared__ float s[];
    uint32_t* su = reinterpret_cast<uint32_t*>(s);
    __half* sh16 = reinterpret_cast<__half*>(s);
    const int t = threadIdx.x, w = t >> 5;
    const int qrow = (t & 31) >> 2, qc = t & 3;
    const int bh = blockIdx.x, bb = bh >> 4, hh = bh & 15;
#pragma unroll
    for (int i = 0; i < 16; ++i) {   // W -> fp16 half2, paired perm
        int idx = t + i * 256, f = idx >> 4, c4 = idx & 15;
        float4 wv = *reinterpret_cast<const float4*>(W_ + f * 64 + c4 * 4);
        su[KW + f * 40 + pp(2 * c4)] = h2(wv.x, wv.y);
        su[KW + f * 40 + pp(2 * c4 + 1)] = h2(wv.z, wv.w);
    }
    {   // Vaug pad rows (row 64 = ones)
        int r = 64 + (t >> 5), c = t & 31;
        su[KVo + r * 36 + c] = (r == 64) ? h2(1.f, 1.f) : 0u;
    }
    const float stab = -0.5f * SC2 * __uint_as_float(g_min_ss);
    float kvacc[2][9][4] = {};
    __syncthreads();
    const int mb = (w >> 2) * 32, nb = (w & 3) * 32;   // GEMM1: 2m x 4n
    const int fb = w * 16;                             // GEMM2: 8 f-slices

    for (int ti = 0; ti < 8; ++ti) {
        const int l0 = ((int)blockIdx.y * 8 + ti) * 64;
#pragma unroll
        for (int i = 0; i < 4; ++i) {
            int idx = t + i * 256, l = idx >> 4, c4 = idx & 15;
            size_t off = ((size_t)(bb * L_ + l0 + l)) * D_ + hh * 64 + c4 * 4;
            float4 kk = *reinterpret_cast<const float4*>(K_ + off);
            su[KX + l * 40 + pp(2 * c4)] = h2(kk.x, kk.y);
            su[KX + l * 40 + pp(2 * c4 + 1)] = h2(kk.z, kk.w);
            float ss = kk.x * kk.x + kk.y * kk.y + kk.z * kk.z + kk.w * kk.w;
            ss += __shfl_xor_sync(~0u, ss, 1);
            ss += __shfl_xor_sync(~0u, ss, 2);
            ss += __shfl_xor_sync(~0u, ss, 4);
            ss += __shfl_xor_sync(~0u, ss, 8);
            if ((t & 15) == 0) s[KH + l] = fmaf(-0.5f * SC2, ss, -stab);
            float4 vv = *reinterpret_cast<const float4*>(V_ + off);
            int hp = pp(l >> 1) * 2 + (l & 1);   // half-position of l
            int d0 = c4 * 4;
            sh16[(KVo + (d0 + 0) * 36) * 2 + hp] = __float2half(vv.x);
            sh16[(KVo + (d0 + 1) * 36) * 2 + hp] = __float2half(vv.y);
            sh16[(KVo + (d0 + 2) * 36) * 2 + hp] = __float2half(vv.z);
            sh16[(KVo + (d0 + 3) * 36) * 2 + hp] = __float2half(vv.w);
        }
        __syncthreads();

#pragma unroll
        for (int h = 0; h < 2; ++h) {
            // ---- GEMM1: S(32x32 per warp) = K x W^T, f-half h ----
            float c[2][4][4] = {};
#pragma unroll
            for (int ks = 0; ks < 4; ++ks) {
                uint32_t a[2][4];
#pragma unroll
                for (int mi = 0; mi < 2; ++mi) {
                    const uint32_t* ap = su + KX + (mb + mi * 16 + qrow) * 40 + ks * 8 + 2 * qc;
                    uint2 lo = *reinterpret_cast<const uint2*>(ap);
                    uint2 hi = *reinterpret_cast<const uint2*>(ap + 8 * 40);
                    a[mi][0] = lo.x; a[mi][1] = hi.x; a[mi][2] = lo.y; a[mi][3] = hi.y;
                }
#pragma unroll
                for (int ni = 0; ni < 4; ++ni) {
                    const uint32_t* bp = su + KW + (h * 128 + nb + ni * 8 + qrow) * 40 + ks * 8 + 2 * qc;
                    uint2 bv = *reinterpret_cast<const uint2*>(bp);
                    uint32_t b2[2] = {bv.x, bv.y};
                    mma16(c[0][ni], a[0], b2);
                    mma16(c[1][ni], a[1], b2);
                }
            }
            // ---- epilogue: k' -> KP[f][l] fp16 (transposed scatter) ----
#pragma unroll
            for (int mi = 0; mi < 2; ++mi) {
                int r0 = mb + mi * 16 + qrow;
                float eb0 = s[KH + r0], eb1 = s[KH + r0 + 8];
                int hp0 = pp(r0 >> 1) * 2 + (r0 & 1);
                int hp1 = pp((r0 + 8) >> 1) * 2 + (r0 & 1);
#pragma unroll
                for (int ni = 0; ni < 4; ++ni) {
                    int fh = nb + ni * 8 + qc * 2;
                    sh16[(KP + fh * 36) * 2 + hp0] =
                        __float2half(INVSQM * (__expf(fmaf(SCALE, c[mi][ni][0], eb0)) + CEPS));
                    sh16[(KP + (fh + 1) * 36) * 2 + hp0] =
                        __float2half(INVSQM * (__expf(fmaf(SCALE, c[mi][ni][1], eb0)) + CEPS));
                    sh16[(KP + fh * 36) * 2 + hp1] =
                        __float2half(INVSQM * (__expf(fmaf(SCALE, c[mi][ni][2], eb1)) + CEPS));
                    sh16[(KP + (fh + 1) * 36) * 2 + hp1] =
                        __float2half(INVSQM * (__expf(fmaf(SCALE, c[mi][ni][3], eb1)) + CEPS));
                }
            }
            __syncthreads();
            // ---- GEMM2: KV[f,72] += k'^T x Vaug, full k=64 per warp ----
#pragma unroll
            for (int ks = 0; ks < 4; ++ks) {
                int kc = ks * 8 + 2 * qc;
                const uint32_t* ap = su + KP + (fb + qrow) * 36 + kc;
                uint2 lo = *reinterpret_cast<const uint2*>(ap);
                uint2 hi = *reinterpret_cast<const uint2*>(ap + 8 * 36);
                uint32_t a2[4] = {lo.x, hi.x, lo.y, hi.y};
#pragma unroll
                for (int ni = 0; ni < 9; ++ni) {
                    const uint32_t* bp = su + KVo + (ni * 8 + qrow) * 36 + kc;
                    uint2 bv = *reinterpret_cast<const uint2*>(bp);
                    uint32_t b2[2] = {bv.x, bv.y};
                    mma16(kvacc[h][ni], a2, b2);
                }
            }
            __syncthreads();
        }
    }
    float* g = g_kv + (size_t)bh * 256 * 72;
#pragma unroll
    for (int h = 0; h < 2; ++h)
#pragma unroll
        for (int ni = 0; ni < 9; ++ni) {
            int f0 = h * 128 + fb + qrow, d0 = ni * 8 + qc * 2;
            atomicAdd(g + f0 * 72 + d0, kvacc[h][ni][0]);
            atomicAdd(g + f0 * 72 + d0 + 1, kvacc[h][ni][1]);
            atomicAdd(g + (f0 + 8) * 72 + d0, kvacc[h][ni][2]);
            atomicAdd(g + (f0 + 8) * 72 + d0 + 1, kvacc[h][ni][3]);
        }
}

// ---------------------------------------------------------------------------
// favor_q: GEMM1 C-frags -> fp16 A-frags in registers (q' never in smem).
// ---------------------------------------------------------------------------
__global__ __launch_bounds__(256, 2) void favor_q(
    const float* __restrict__ Q_, const float* __restrict__ W_,
    float* __restrict__ O_) {
    extern __shared__ float s[];
    uint32_t* su = reinterpret_cast<uint32_t*>(s);
    __half* sh16 = reinterpret_cast<__half*>(s);
    const int t = threadIdx.x, w = t >> 5, lane = t & 31;
    const int qrow = lane >> 2, qc = t & 3;
    const int bh = blockIdx.x, bb = bh >> 4, hh = bh & 15;
#pragma unroll
    for (int i = 0; i < 16; ++i) {
        int idx = t + i * 256, f = idx >> 4, c4 = idx & 15;
        float4 wv = *reinterpret_cast<const float4*>(W_ + f * 64 + c4 * 4);
        su[QW + f * 40 + pp(2 * c4)] = h2(wv.x, wv.y);
        su[QW + f * 40 + pp(2 * c4 + 1)] = h2(wv.z, wv.w);
    }
    {   // KV^T [d][f] fp16, paired perm on f half2-idx
        const float* g = g_kv + (size_t)bh * 256 * 72;
        for (int i = t; i < 256 * 72; i += 256) {
            int f = i / 72, d = i - f * 72;
            sh16[(QKV + d * 136 + pp(f >> 1)) * 2 + (f & 1)] = __float2half(g[i]);
        }
    }
    __syncthreads();
    const int ms = (w & 3) * 16, fg = w >> 2;

    for (int ti = 0; ti < 8; ++ti) {
        const int l0 = ((int)blockIdx.y * 8 + ti) * 64;
#pragma unroll
        for (int i = 0; i < 4; ++i) {
            int idx = t + i * 256, l = idx >> 4, c4 = idx & 15;
            size_t off = ((size_t)(bb * L_ + l0 + l)) * D_ + hh * 64 + c4 * 4;
            float4 qq = *reinterpret_cast<const float4*>(Q_ + off);
            su[QT + l * 40 + pp(2 * c4)] = h2(qq.x, qq.y);
            su[QT + l * 40 + pp(2 * c4 + 1)] = h2(qq.z, qq.w);
        }
        __syncthreads();
        // ---- GEMM1: S(16m x 128n per warp), n-range fg*128 ----
        float c[16][4] = {};
#pragma unroll
        for (int ks = 0; ks < 4; ++ks) {
            const uint32_t* ap = su + QT + (ms + qrow) * 40 + ks * 8 + 2 * qc;
            uint2 lo = *reinterpret_cast<const uint2*>(ap);
            uint2 hi = *reinterpret_cast<const uint2*>(ap + 8 * 40);
            uint32_t a2[4] = {lo.x, hi.x, lo.y, hi.y};
#pragma unroll
            for (int ni = 0; ni < 16; ++ni) {
                const uint32_t* bp = su + QW + (fg * 128 + ni * 8 + qrow) * 40 + ks * 8 + 2 * qc;
                uint2 bv = *reinterpret_cast<const uint2*>(bp);
                uint32_t b2[2] = {bv.x, bv.y};
                mma16(c[ni], a2, b2);
            }
        }
        // ---- epilogue: exp + pack C pairs -> fp16 A-frags (k=16 each) ----
        uint32_t cu[8][4];
#pragma unroll
        for (int j = 0; j < 8; ++j) {
            float v00 = INVSQM * (__expf(SCALE * c[2 * j][0]) + CEPS);
            float v01 = INVSQM * (__expf(SCALE * c[2 * j][1]) + CEPS);
            float v02 = INVSQM * (__expf(SCALE * c[2 * j][2]) + CEPS);
            float v03 = INVSQM * (__expf(SCALE * c[2 * j][3]) + CEPS);
            float v10 = INVSQM * (__expf(SCALE * c[2 * j + 1][0]) + CEPS);
            float v11 = INVSQM * (__expf(SCALE * c[2 * j + 1][1]) + CEPS);
            float v12 = INVSQM * (__expf(SCALE * c[2 * j + 1][2]) + CEPS);
            float v13 = INVSQM * (__expf(SCALE * c[2 * j + 1][3]) + CEPS);
            cu[j][0] = h2(v00, v01);
            cu[j][1] = h2(v02, v03);
            cu[j][2] = h2(v10, v11);
            cu[j][3] = h2(v12, v13);
        }
        // ---- GEMM3: out[16m x 72] partial over f-range fg*128 ----
        float o[9][4] = {};
#pragma unroll
        for (int j = 0; j < 8; ++j) {
#pragma unroll
            for (int ni = 0; ni < 9; ++ni) {
                const uint32_t* bp = su + QKV + (ni * 8 + qrow) * 136 + fg * 64 + j * 8 + 2 * qc;
                uint2 bv = *reinterpret_cast<const uint2*>(bp);
                uint32_t b2[2] = {bv.x, bv.y};
                mma16(o[ni], cu[j], b2);
            }
        }
        __syncthreads();
        if (fg == 1) {
            int r0 = ms + qrow;
#pragma unroll
            for (int ni = 0; ni < 9; ++ni) {
                int col = ni * 8 + 2 * qc;
                *reinterpret_cast<float2*>(s + QOP + r0 * 72 + col) =
                    make_float2(o[ni][0], o[ni][1]);
                *reinterpret_cast<float2*>(s + QOP + (r0 + 8) * 72 + col) =
                    make_float2(o[ni][2], o[ni][3]);
            }
        }
        __syncthreads();
        if (fg == 0) {
            int r0 = ms + qrow;
#pragma unroll
            for (int ni = 0; ni < 9; ++ni) {
                int col = ni * 8 + 2 * qc;
                float2 p0 = *reinterpret_cast<const float2*>(s + QOP + r0 * 72 + col);
                float2 p1 = *reinterpret_cast<const float2*>(s + QOP + (r0 + 8) * 72 + col);
                o[ni][0] += p0.x; o[ni][1] += p0.y;
                o[ni][2] += p1.x; o[ni][3] += p1.y;
            }
            float den0 = __shfl_sync(~0u, o[8][0], lane & ~3);
            float den1 = __shfl_sync(~0u, o[8][2], lane & ~3);
            if (fabsf(den0) <= CEPS) den0 += 2.f * CEPS;
            if (fabsf(den1) <= CEPS) den1 += 2.f * CEPS;
            float inv0 = 1.f / den0, inv1 = 1.f / den1;
            float* op0 = O_ + ((size_t)(bb * L_ + l0 + r0)) * D_ + hh * 64;
            float* op1 = op0 + 8 * D_;
#pragma unroll
            for (int ni = 0; ni < 8; ++ni) {
                int col = ni * 8 + 2 * qc;
                *reinterpret_cast<float2*>(op0 + col) =
                    make_float2(o[ni][0] * inv0, o[ni][1] * inv0);
                *reinterpret_cast<float2*>(op1 + col) =
                    make_float2(o[ni][2] * inv1, o[ni][3] * inv1);
            }
        }
    }
}

// ---------------------------------------------------------------------------
extern "C" void kernel_launch(void* const* d_in, const int* in_sizes, int n_in,
                              void* d_out, int out_size) {
    const float* q = (const float*)d_in[0];
    const float* k = (const float*)d_in[1];
    const float* v = (const float*)d_in[2];
    const float* w = (const float*)d_in[3];
    float* out = (float*)d_out;

    cudaFuncSetAttribute(favor_k, cudaFuncAttributeMaxDynamicSharedMemorySize, KFL * 4);
    cudaFuncSetAttribute(favor_q, cudaFuncAttributeMaxDynamicSharedMemorySize, QFL * 4);

    init_kernel<<<1, 1>>>();
    min_kernel<<<1024, 256>>>(k);
    favor_k<<<dim3(64, 8), 256, KFL * 4>>>(k, v, w);
    favor_q<<<dim3(64, 8), 256, QFL * 4>>>(q, w, out);
}

// round 14
// speedup vs baseline: 2.8797x; 1.1466x over previous
#include <cuda_runtime.h>
#include <cuda_fp16.h>
#include <cstdint>

// FAVOR+ attention via mma.sync m16n8k16 fp16 (fp32 accum) + ldmatrix fragment
// loads. 256-thread CTAs, 2 CTAs/SM. B=4, L=4096, D=1024, H=16 x d=64, m=256.

namespace {
constexpr int L_ = 4096, D_ = 1024;
constexpr float SCALE = 0.17677669529663687f, SC2 = SCALE * SCALE;
constexpr float CEPS = 1e-4f, INVSQM = 0.0625f;
// favor_k smem (uint32 word offsets); row strides 36 words (ldmatrix conflict-free)
constexpr int KW = 0;          // W    [256 f][36]  (32 half2 data)
constexpr int KX = 9216;       // K    [64 l][36]
constexpr int KVo = 11520;     // Vaug [72 d'][36]  (row 64 = ones)
constexpr int KP = 14112;      // k'   [128 f][36]
constexpr int KH = 18720;      // eb[64] fp32
constexpr int KFL = 18784;     // 75136 B (x2 CTA = 150 KB)
// favor_q smem
constexpr int QW = 0;          // W    [256 f][36]
constexpr int QT = 9216;       // Q    [64 l][36]
constexpr int QKV = 11520;     // KV^T [72 d'][132] (128 half2 f)
constexpr int QOP = 21024;     // out partials [64][72] fp32
constexpr int QFL = 25632;     // 102528 B (x2 CTA = 205 KB)
}

__device__ float g_kv[64 * 256 * 72];   // [bh][f][d'(64=ksum)]
__device__ unsigned g_min_ss;

__device__ __forceinline__ uint32_t h2(float a, float b) {
    __half2 h = __floats2half2_rn(a, b);
    return *reinterpret_cast<uint32_t*>(&h);
}
__device__ __forceinline__ void mma16(float* c, const uint32_t* a, const uint32_t* b) {
    asm volatile(
        "mma.sync.aligned.m16n8k16.row.col.f32.f16.f16.f32 "
        "{%0,%1,%2,%3},{%4,%5,%6,%7},{%8,%9},{%0,%1,%2,%3};"
        : "+f"(c[0]), "+f"(c[1]), "+f"(c[2]), "+f"(c[3])
        : "r"(a[0]), "r"(a[1]), "r"(a[2]), "r"(a[3]), "r"(b[0]), "r"(b[1]));
}
__device__ __forceinline__ void ldsm4(uint32_t* r, uint32_t a) {
    asm volatile("ldmatrix.sync.aligned.m8n8.x4.shared.b16 {%0,%1,%2,%3}, [%4];"
        : "=r"(r[0]), "=r"(r[1]), "=r"(r[2]), "=r"(r[3]) : "r"(a));
}
__device__ __forceinline__ void ldsm2(uint32_t* r, uint32_t a) {
    asm volatile("ldmatrix.sync.aligned.m8n8.x2.shared.b16 {%0,%1}, [%2];"
        : "=r"(r[0]), "=r"(r[1]) : "r"(a));
}

// ---------------------------------------------------------------------------
__global__ void init_kernel() { g_min_ss = 0x7F800000u; }

__global__ __launch_bounds__(256) void min_kernel(const float* __restrict__ Kp) {
    int t = threadIdx.x;
    {   // zero scratch
        size_t tid = (size_t)blockIdx.x * 256 + t;
        constexpr size_t n = (size_t)64 * 256 * 72;
        for (size_t i = tid; i < n; i += (size_t)gridDim.x * 256) g_kv[i] = 0.f;
    }
    float mn = 3.4028235e38f;
#pragma unroll
    for (int it = 0; it < 16; ++it) {
        size_t ch = (size_t)blockIdx.x * 256 + it * 16 + (t >> 4);
        float4 v4 = *reinterpret_cast<const float4*>(Kp + ch * 64 + (t & 15) * 4);
        float ss = v4.x * v4.x + v4.y * v4.y + v4.z * v4.z + v4.w * v4.w;
        ss += __shfl_xor_sync(~0u, ss, 8); ss += __shfl_xor_sync(~0u, ss, 4);
        ss += __shfl_xor_sync(~0u, ss, 2); ss += __shfl_xor_sync(~0u, ss, 1);
        mn = fminf(mn, ss);
    }
    mn = fminf(mn, __shfl_xor_sync(~0u, mn, 16));
    __shared__ float wmin[8];
    if ((t & 31) == 0) wmin[t >> 5] = mn;
    __syncthreads();
    if (t < 8) {
        float m2 = wmin[t];
        m2 = fminf(m2, __shfl_xor_sync(0xffu, m2, 4));
        m2 = fminf(m2, __shfl_xor_sync(0xffu, m2, 2));
        m2 = fminf(m2, __shfl_xor_sync(0xffu, m2, 1));
        if (t == 0) atomicMin(&g_min_ss, __float_as_uint(m2));
    }
}

// ---------------------------------------------------------------------------
__global__ __launch_bounds__(256, 2) void favor_k(
    const float* __restrict__ K_, const float* __restrict__ V_,
    const float* __restrict__ W_) {
    extern __shared__ float s[];
    uint32_t* su = reinterpret_cast<uint32_t*>(s);
    __half* sh16 = reinterpret_cast<__half*>(s);
    const uint32_t sb = (uint32_t)__cvta_generic_to_shared(s);
    const int t = threadIdx.x, w = t >> 5, lane = t & 31;
    const int qrow = lane >> 2, qc = lane & 3;
    const int bh = blockIdx.x, bb = bh >> 4, hh = bh & 15;
#pragma unroll
    for (int i = 0; i < 16; ++i) {   // W natural k-order
        int idx = t + i * 256, f = idx >> 4, c4 = idx & 15;
        float4 wv = *reinterpret_cast<const float4*>(W_ + f * 64 + c4 * 4);
        *reinterpret_cast<uint2*>(su + KW + f * 36 + 2 * c4) =
            make_uint2(h2(wv.x, wv.y), h2(wv.z, wv.w));
    }
    {   // Vaug pad rows (row 64 = ones)
        int r = 64 + (t >> 5), c = t & 31;
        su[KVo + r * 36 + c] = (r == 64) ? h2(1.f, 1.f) : 0u;
    }
    const float stab = -0.5f * SC2 * __uint_as_float(g_min_ss);
    float kvacc[2][9][4] = {};
    __syncthreads();
    const int mb = (w >> 2) * 32, nb = (w & 3) * 32;   // GEMM1: 2m x 4n
    const int fb = w * 16;                             // GEMM2: 8 f-slices
    // ldmatrix per-lane address components
    const int lrow = lane & 15;
    const int khi = (lane >> 4) * 16;                  // A: k-offset bytes
    const int bko = (lane & 8) ? 16 : 0;               // B: k-offset bytes
    const int brow = (lane & 7) + ((lane & 16) ? 8 : 0);
    const uint32_t aA = sb + (KX + (mb + lrow) * 36) * 4 + khi;
    const uint32_t aP = sb + (KP + (fb + lrow) * 36) * 4 + khi;
    const uint32_t bV = sb + (KVo + brow * 36) * 4 + bko;
    const uint32_t bV8 = sb + (KVo + (64 + (lane & 7)) * 36) * 4 + bko;

    for (int ti = 0; ti < 8; ++ti) {
        const int l0 = ((int)blockIdx.y * 8 + ti) * 64;
#pragma unroll
        for (int i = 0; i < 4; ++i) {
            int idx = t + i * 256, l = idx >> 4, c4 = idx & 15;
            size_t off = ((size_t)(bb * L_ + l0 + l)) * D_ + hh * 64 + c4 * 4;
            float4 kk = *reinterpret_cast<const float4*>(K_ + off);
            *reinterpret_cast<uint2*>(su + KX + l * 36 + 2 * c4) =
                make_uint2(h2(kk.x, kk.y), h2(kk.z, kk.w));
            float ss = kk.x * kk.x + kk.y * kk.y + kk.z * kk.z + kk.w * kk.w;
            ss += __shfl_xor_sync(~0u, ss, 1);
            ss += __shfl_xor_sync(~0u, ss, 2);
            ss += __shfl_xor_sync(~0u, ss, 4);
            ss += __shfl_xor_sync(~0u, ss, 8);
            if ((t & 15) == 0) s[KH + l] = fmaf(-0.5f * SC2, ss, -stab);
            float4 vv = *reinterpret_cast<const float4*>(V_ + off);
            int d0 = c4 * 4;
            sh16[(KVo + (d0 + 0) * 36) * 2 + l] = __float2half(vv.x);
            sh16[(KVo + (d0 + 1) * 36) * 2 + l] = __float2half(vv.y);
            sh16[(KVo + (d0 + 2) * 36) * 2 + l] = __float2half(vv.z);
            sh16[(KVo + (d0 + 3) * 36) * 2 + l] = __float2half(vv.w);
        }
        __syncthreads();

#pragma unroll
        for (int h = 0; h < 2; ++h) {
            const uint32_t bW = sb + (KW + (h * 128 + nb + brow) * 36) * 4 + bko;
            // ---- GEMM1: S(32x32 per warp) = K x W^T, f-half h ----
            float c[2][4][4] = {};
#pragma unroll
            for (int ks = 0; ks < 4; ++ks) {
                uint32_t a0[4], a1[4], b0[4], b1[4];
                ldsm4(a0, aA + ks * 32);
                ldsm4(a1, aA + 16 * 144 + ks * 32);
                ldsm4(b0, bW + ks * 32);
                ldsm4(b1, bW + 2304 + ks * 32);
                mma16(c[0][0], a0, b0); mma16(c[0][1], a0, b0 + 2);
                mma16(c[0][2], a0, b1); mma16(c[0][3], a0, b1 + 2);
                mma16(c[1][0], a1, b0); mma16(c[1][1], a1, b0 + 2);
                mma16(c[1][2], a1, b1); mma16(c[1][3], a1, b1 + 2);
            }
            // ---- epilogue: k' -> KP[f][l] fp16 (transposed scatter) ----
#pragma unroll
            for (int mi = 0; mi < 2; ++mi) {
                int r0 = mb + mi * 16 + qrow;
                float eb0 = s[KH + r0], eb1 = s[KH + r0 + 8];
#pragma unroll
                for (int ni = 0; ni < 4; ++ni) {
                    int fh = nb + ni * 8 + qc * 2;
                    sh16[(KP + fh * 36) * 2 + r0] =
                        __float2half(INVSQM * (__expf(fmaf(SCALE, c[mi][ni][0], eb0)) + CEPS));
                    sh16[(KP + (fh + 1) * 36) * 2 + r0] =
                        __float2half(INVSQM * (__expf(fmaf(SCALE, c[mi][ni][1], eb0)) + CEPS));
                    sh16[(KP + fh * 36) * 2 + r0 + 8] =
                        __float2half(INVSQM * (__expf(fmaf(SCALE, c[mi][ni][2], eb1)) + CEPS));
                    sh16[(KP + (fh + 1) * 36) * 2 + r0 + 8] =
                        __float2half(INVSQM * (__expf(fmaf(SCALE, c[mi][ni][3], eb1)) + CEPS));
                }
            }
            __syncthreads();
            // ---- GEMM2: KV[f,72] += k'^T x Vaug, full k=64 per warp ----
#pragma unroll
            for (int ks = 0; ks < 4; ++ks) {
                uint32_t a2[4], bv0[4], bv1[4], bv2[4], bv3[4], bv8[2];
                ldsm4(a2, aP + ks * 32);
                ldsm4(bv0, bV + ks * 32);
                ldsm4(bv1, bV + 2304 + ks * 32);
                ldsm4(bv2, bV + 4608 + ks * 32);
                ldsm4(bv3, bV + 6912 + ks * 32);
                ldsm2(bv8, bV8 + ks * 32);
                mma16(kvacc[h][0], a2, bv0); mma16(kvacc[h][1], a2, bv0 + 2);
                mma16(kvacc[h][2], a2, bv1); mma16(kvacc[h][3], a2, bv1 + 2);
                mma16(kvacc[h][4], a2, bv2); mma16(kvacc[h][5], a2, bv2 + 2);
                mma16(kvacc[h][6], a2, bv3); mma16(kvacc[h][7], a2, bv3 + 2);
                mma16(kvacc[h][8], a2, bv8);
            }
            __syncthreads();
        }
    }
    float* g = g_kv + (size_t)bh * 256 * 72;
#pragma unroll
    for (int h = 0; h < 2; ++h)
#pragma unroll
        for (int ni = 0; ni < 9; ++ni) {
            int f0 = h * 128 + fb + qrow, d0 = ni * 8 + qc * 2;
            atomicAdd(g + f0 * 72 + d0, kvacc[h][ni][0]);
            atomicAdd(g + f0 * 72 + d0 + 1, kvacc[h][ni][1]);
            atomicAdd(g + (f0 + 8) * 72 + d0, kvacc[h][ni][2]);
            atomicAdd(g + (f0 + 8) * 72 + d0 + 1, kvacc[h][ni][3]);
        }
}

// ---------------------------------------------------------------------------
// favor_q: GEMM1 C-frags -> fp16 A-frags in registers (q' never in smem).
// ---------------------------------------------------------------------------
__global__ __launch_bounds__(256, 2) void favor_q(
    const float* __restrict__ Q_, const float* __restrict__ W_,
    float* __restrict__ O_) {
    extern __shared__ float s[];
    uint32_t* su = reinterpret_cast<uint32_t*>(s);
    __half* sh16 = reinterpret_cast<__half*>(s);
    const uint32_t sb = (uint32_t)__cvta_generic_to_shared(s);
    const int t = threadIdx.x, w = t >> 5, lane = t & 31;
    const int qrow = lane >> 2, qc = lane & 3;
    const int bh = blockIdx.x, bb = bh >> 4, hh = bh & 15;
#pragma unroll
    for (int i = 0; i < 16; ++i) {
        int idx = t + i * 256, f = idx >> 4, c4 = idx & 15;
        float4 wv = *reinterpret_cast<const float4*>(W_ + f * 64 + c4 * 4);
        *reinterpret_cast<uint2*>(su + QW + f * 36 + 2 * c4) =
            make_uint2(h2(wv.x, wv.y), h2(wv.z, wv.w));
    }
    {   // KV^T [d'][f] fp16, natural f order
        const float* g = g_kv + (size_t)bh * 256 * 72;
        for (int i = t; i < 256 * 72; i += 256) {
            int f = i / 72, d = i - f * 72;
            sh16[(QKV + d * 132) * 2 + f] = __float2half(g[i]);
        }
    }
    __syncthreads();
    const int ms = (w & 3) * 16, fg = w >> 2;
    const int lrow = lane & 15;
    const int khi = (lane >> 4) * 16;
    const int bko = (lane & 8) ? 16 : 0;
    const int brow = (lane & 7) + ((lane & 16) ? 8 : 0);
    const uint32_t aQ = sb + (QT + (ms + lrow) * 36) * 4 + khi;
    const uint32_t bW = sb + (QW + (fg * 128 + brow) * 36) * 4 + bko;
    const uint32_t bK = sb + (QKV + brow * 132) * 4 + fg * 256 + bko;
    const uint32_t bK8 = sb + (QKV + (64 + (lane & 7)) * 132) * 4 + fg * 256 + bko;

    for (int ti = 0; ti < 8; ++ti) {
        const int l0 = ((int)blockIdx.y * 8 + ti) * 64;
#pragma unroll
        for (int i = 0; i < 4; ++i) {
            int idx = t + i * 256, l = idx >> 4, c4 = idx & 15;
            size_t off = ((size_t)(bb * L_ + l0 + l)) * D_ + hh * 64 + c4 * 4;
            float4 qq = *reinterpret_cast<const float4*>(Q_ + off);
            *reinterpret_cast<uint2*>(su + QT + l * 36 + 2 * c4) =
                make_uint2(h2(qq.x, qq.y), h2(qq.z, qq.w));
        }
        __syncthreads();
        // ---- GEMM1: S(16m x 128n per warp), n-range fg*128 ----
        float c[16][4] = {};
#pragma unroll
        for (int ks = 0; ks < 4; ++ks) {
            uint32_t a2[4];
            ldsm4(a2, aQ + ks * 32);
#pragma unroll
            for (int p = 0; p < 8; ++p) {
                uint32_t bp[4];
                ldsm4(bp, bW + p * 2304 + ks * 32);
                mma16(c[2 * p], a2, bp);
                mma16(c[2 * p + 1], a2, bp + 2);
            }
        }
        // ---- epilogue: exp + pack C pairs -> fp16 A-frags (k=16 each) ----
        uint32_t cu[8][4];
#pragma unroll
        for (int j = 0; j < 8; ++j) {
            float v00 = INVSQM * (__expf(SCALE * c[2 * j][0]) + CEPS);
            float v01 = INVSQM * (__expf(SCALE * c[2 * j][1]) + CEPS);
            float v02 = INVSQM * (__expf(SCALE * c[2 * j][2]) + CEPS);
            float v03 = INVSQM * (__expf(SCALE * c[2 * j][3]) + CEPS);
            float v10 = INVSQM * (__expf(SCALE * c[2 * j + 1][0]) + CEPS);
            float v11 = INVSQM * (__expf(SCALE * c[2 * j + 1][1]) + CEPS);
            float v12 = INVSQM * (__expf(SCALE * c[2 * j + 1][2]) + CEPS);
            float v13 = INVSQM * (__expf(SCALE * c[2 * j + 1][3]) + CEPS);
            cu[j][0] = h2(v00, v01);
            cu[j][1] = h2(v02, v03);
            cu[j][2] = h2(v10, v11);
            cu[j][3] = h2(v12, v13);
        }
        // ---- GEMM3: out[16m x 72] partial over f-range fg*128 ----
        float o[9][4] = {};
#pragma unroll
        for (int j = 0; j < 8; ++j) {
            uint32_t bv0[4], bv1[4], bv2[4], bv3[4], bv8[2];
            ldsm4(bv0, bK + j * 32);
            ldsm4(bv1, bK + 8448 + j * 32);
            ldsm4(bv2, bK + 16896 + j * 32);
            ldsm4(bv3, bK + 25344 + j * 32);
            ldsm2(bv8, bK8 + j * 32);
            mma16(o[0], cu[j], bv0); mma16(o[1], cu[j], bv0 + 2);
            mma16(o[2], cu[j], bv1); mma16(o[3], cu[j], bv1 + 2);
            mma16(o[4], cu[j], bv2); mma16(o[5], cu[j], bv2 + 2);
            mma16(o[6], cu[j], bv3); mma16(o[7], cu[j], bv3 + 2);
            mma16(o[8], cu[j], bv8);
        }
        __syncthreads();
        if (fg == 1) {
            int r0 = ms + qrow;
#pragma unroll
            for (int ni = 0; ni < 9; ++ni) {
                int col = ni * 8 + 2 * qc;
                *reinterpret_cast<float2*>(s + QOP + r0 * 72 + col) =
                    make_float2(o[ni][0], o[ni][1]);
                *reinterpret_cast<float2*>(s + QOP + (r0 + 8) * 72 + col) =
                    make_float2(o[ni][2], o[ni][3]);
            }
        }
        __syncthreads();
        if (fg == 0) {
            int r0 = ms + qrow;
#pragma unroll
            for (int ni = 0; ni < 9; ++ni) {
                int col = ni * 8 + 2 * qc;
                float2 p0 = *reinterpret_cast<const float2*>(s + QOP + r0 * 72 + col);
                float2 p1 = *reinterpret_cast<const float2*>(s + QOP + (r0 + 8) * 72 + col);
                o[ni][0] += p0.x; o[ni][1] += p0.y;
                o[ni][2] += p1.x; o[ni][3] += p1.y;
            }
            float den0 = __shfl_sync(~0u, o[8][0], lane & ~3);
            float den1 = __shfl_sync(~0u, o[8][2], lane & ~3);
            if (fabsf(den0) <= CEPS) den0 += 2.f * CEPS;
            if (fabsf(den1) <= CEPS) den1 += 2.f * CEPS;
            float inv0 = 1.f / den0, inv1 = 1.f / den1;
            float* op0 = O_ + ((size_t)(bb * L_ + l0 + r0)) * D_ + hh * 64;
            float* op1 = op0 + 8 * D_;
#pragma unroll
            for (int ni = 0; ni < 8; ++ni) {
                int col = ni * 8 + 2 * qc;
                *reinterpret_cast<float2*>(op0 + col) =
                    make_float2(o[ni][0] * inv0, o[ni][1] * inv0);
                *reinterpret_cast<float2*>(op1 + col) =
                    make_float2(o[ni][2] * inv1, o[ni][3] * inv1);
            }
        }
    }
}

// ---------------------------------------------------------------------------
extern "C" void kernel_launch(void* const* d_in, const int* in_sizes, int n_in,
                              void* d_out, int out_size) {
    const float* q = (const float*)d_in[0];
    const float* k = (const float*)d_in[1];
    const float* v = (const float*)d_in[2];
    const float* w = (const float*)d_in[3];
    float* out = (float*)d_out;

    cudaFuncSetAttribute(favor_k, cudaFuncAttributeMaxDynamicSharedMemorySize, KFL * 4);
    cudaFuncSetAttribute(favor_q, cudaFuncAttributeMaxDynamicSharedMemorySize, QFL * 4);

    init_kernel<<<1, 1>>>();
    min_kernel<<<1024, 256>>>(k);
    favor_k<<<dim3(64, 8), 256, KFL * 4>>>(k, v, w);
    favor_q<<<dim3(64, 8), 256, QFL * 4>>>(q, w, out);
}

// round 15
// speedup vs baseline: 3.1803x; 1.1044x over previous
#include <cuda_runtime.h>
#include <cuda_fp16.h>
#include <cstdint>

// FAVOR+ attention via mma.sync m16n8k16 fp16 (fp32 accum) + ldmatrix(+trans).
// 256-thread CTAs, 2 CTAs/SM. B=4, L=4096, D=1024, H=16 x d=64, m=256.

namespace {
constexpr int L_ = 4096, D_ = 1024;
constexpr float SCALE = 0.17677669529663687f, SC2 = SCALE * SCALE;
constexpr float CEPS = 1e-4f, INVSQM = 0.0625f;
// favor_k smem (uint32 word offsets)
constexpr int KW = 0;          // W    [256 f][36]   (32 data words)
constexpr int KX = 9216;       // K    [64 l][36]
constexpr int KVo = 11520;     // Vaug [64 l][36]    natural; cols 64..71 = aug
constexpr int KP = 13824;      // k'   [64 l][132]   natural [l][f], 128 data words
constexpr int KH = 22272;      // eb[64] fp32
constexpr int KFL = 22336;     // 89344 B (x2 CTA = 178.7 KB)
// favor_q smem
constexpr int QW = 0;          // W    [256 f][36]
constexpr int QT = 9216;       // Q    [64 l][36]
constexpr int QKV = 11520;     // KV^T [72 d'][132]
constexpr int QOP = 21024;     // out partials [64][72] fp32
constexpr int QFL = 25632;     // 102528 B (x2 CTA = 205 KB)
}

__device__ float g_kv[64 * 256 * 72];   // [bh][f][d'(64=ksum)]
__device__ unsigned g_min_ss;

__device__ __forceinline__ uint32_t h2(float a, float b) {
    __half2 h = __floats2half2_rn(a, b);
    return *reinterpret_cast<uint32_t*>(&h);
}
__device__ __forceinline__ void mma16(float* c, const uint32_t* a, const uint32_t* b) {
    asm volatile(
        "mma.sync.aligned.m16n8k16.row.col.f32.f16.f16.f32 "
        "{%0,%1,%2,%3},{%4,%5,%6,%7},{%8,%9},{%0,%1,%2,%3};"
        : "+f"(c[0]), "+f"(c[1]), "+f"(c[2]), "+f"(c[3])
        : "r"(a[0]), "r"(a[1]), "r"(a[2]), "r"(a[3]), "r"(b[0]), "r"(b[1]));
}
__device__ __forceinline__ void ldsm4(uint32_t* r, uint32_t a) {
    asm volatile("ldmatrix.sync.aligned.m8n8.x4.shared.b16 {%0,%1,%2,%3}, [%4];"
        : "=r"(r[0]), "=r"(r[1]), "=r"(r[2]), "=r"(r[3]) : "r"(a));
}
__device__ __forceinline__ void ldsm2(uint32_t* r, uint32_t a) {
    asm volatile("ldmatrix.sync.aligned.m8n8.x2.shared.b16 {%0,%1}, [%2];"
        : "=r"(r[0]), "=r"(r[1]) : "r"(a));
}
__device__ __forceinline__ void ldsm4t(uint32_t* r, uint32_t a) {
    asm volatile("ldmatrix.sync.aligned.m8n8.x4.trans.shared.b16 {%0,%1,%2,%3}, [%4];"
        : "=r"(r[0]), "=r"(r[1]), "=r"(r[2]), "=r"(r[3]) : "r"(a));
}
__device__ __forceinline__ void ldsm2t(uint32_t* r, uint32_t a) {
    asm volatile("ldmatrix.sync.aligned.m8n8.x2.trans.shared.b16 {%0,%1}, [%2];"
        : "=r"(r[0]), "=r"(r[1]) : "r"(a));
}

// ---------------------------------------------------------------------------
__global__ void init_kernel() { g_min_ss = 0x7F800000u; }

__global__ __launch_bounds__(256) void min_kernel(const float* __restrict__ Kp) {
    int t = threadIdx.x;
    {   // zero scratch
        size_t tid = (size_t)blockIdx.x * 256 + t;
        constexpr size_t n = (size_t)64 * 256 * 72;
        for (size_t i = tid; i < n; i += (size_t)gridDim.x * 256) g_kv[i] = 0.f;
    }
    float mn = 3.4028235e38f;
#pragma unroll
    for (int it = 0; it < 16; ++it) {
        size_t ch = (size_t)blockIdx.x * 256 + it * 16 + (t >> 4);
        float4 v4 = *reinterpret_cast<const float4*>(Kp + ch * 64 + (t & 15) * 4);
        float ss = v4.x * v4.x + v4.y * v4.y + v4.z * v4.z + v4.w * v4.w;
        ss += __shfl_xor_sync(~0u, ss, 8); ss += __shfl_xor_sync(~0u, ss, 4);
        ss += __shfl_xor_sync(~0u, ss, 2); ss += __shfl_xor_sync(~0u, ss, 1);
        mn = fminf(mn, ss);
    }
    mn = fminf(mn, __shfl_xor_sync(~0u, mn, 16));
    __shared__ float wmin[8];
    if ((t & 31) == 0) wmin[t >> 5] = mn;
    __syncthreads();
    if (t < 8) {
        float m2 = wmin[t];
        m2 = fminf(m2, __shfl_xor_sync(0xffu, m2, 4));
        m2 = fminf(m2, __shfl_xor_sync(0xffu, m2, 2));
        m2 = fminf(m2, __shfl_xor_sync(0xffu, m2, 1));
        if (t == 0) atomicMin(&g_min_ss, __float_as_uint(m2));
    }
}

// ---------------------------------------------------------------------------
// favor_k: natural-layout V/k' + ldmatrix.trans GEMM2. Per 64-row tile:
//   GEMM1 both f-halves -> epilogue (vectorized STS, [l][f]) -> one sync ->
//   GEMM2 (A = k'^T via trans, B = Vaug^T via trans, B shared by both f-tiles).
// ---------------------------------------------------------------------------
__global__ __launch_bounds__(256, 2) void favor_k(
    const float* __restrict__ K_, const float* __restrict__ V_,
    const float* __restrict__ W_) {
    extern __shared__ float s[];
    uint32_t* su = reinterpret_cast<uint32_t*>(s);
    const uint32_t sb = (uint32_t)__cvta_generic_to_shared(s);
    const int t = threadIdx.x, w = t >> 5, lane = t & 31;
    const int qrow = lane >> 2, qc = lane & 3;
    const int bh = blockIdx.x, bb = bh >> 4, hh = bh & 15;
#pragma unroll
    for (int i = 0; i < 16; ++i) {   // W natural k-order
        int idx = t + i * 256, f = idx >> 4, c4 = idx & 15;
        float4 wv = *reinterpret_cast<const float4*>(W_ + f * 64 + c4 * 4);
        *reinterpret_cast<uint2*>(su + KW + f * 36 + 2 * c4) =
            make_uint2(h2(wv.x, wv.y), h2(wv.z, wv.w));
    }
    // Vaug static columns 64..71 (word 32 = {1,0}, words 33..35 = 0)
    su[KVo + (t & 63) * 36 + 32 + (t >> 6)] = ((t >> 6) == 0) ? h2(1.f, 0.f) : 0u;
    const float stab = -0.5f * SC2 * __uint_as_float(g_min_ss);
    float kvacc[2][9][4] = {};
    __syncthreads();
    const int mb = (w >> 2) * 32, nb = (w & 3) * 32;   // GEMM1: 2m x 4n (per half)
    const int fb = w * 16;                             // GEMM2: f-slice per warp
    // ldmatrix per-lane address components
    const int lrow = lane & 15;
    const int khi = (lane >> 4) * 16;                  // GEMM1 A k-offset bytes
    const int bko = (lane & 8) ? 16 : 0;               // GEMM1 B k-offset bytes
    const int brow = (lane & 7) + ((lane & 16) ? 8 : 0);
    const uint32_t aA = sb + (KX + (mb + lrow) * 36) * 4 + khi;
    // GEMM2 A (k'^T, trans): lanes 0-7: l0-7@f+0 | 8-15: l0-7@f+8 | 16-23: l8-15@f+0 | 24-31: l8-15@f+8
    const int a2row = (lane & 7) + ((lane & 16) ? 8 : 0);
    const int a2foff = (lane & 8) ? 8 : 0;             // halfs
    const uint32_t aP = sb + (KP + a2row * 132) * 4 + (fb + a2foff) * 2;
    // GEMM2 B (Vaug^T, trans): lanes 0-15: rows l0-15 @ d+0 | 16-31: rows l0-15 @ d+8
    const uint32_t bV = sb + (KVo + lrow * 36) * 4 + ((lane & 16) ? 16 : 0);
    const uint32_t bV8 = sb + (KVo + lrow * 36) * 4 + 128;   // d' 64..71

    for (int ti = 0; ti < 8; ++ti) {
        const int l0 = ((int)blockIdx.y * 8 + ti) * 64;
#pragma unroll
        for (int i = 0; i < 4; ++i) {
            int idx = t + i * 256, l = idx >> 4, c4 = idx & 15;
            size_t off = ((size_t)(bb * L_ + l0 + l)) * D_ + hh * 64 + c4 * 4;
            float4 kk = *reinterpret_cast<const float4*>(K_ + off);
            *reinterpret_cast<uint2*>(su + KX + l * 36 + 2 * c4) =
                make_uint2(h2(kk.x, kk.y), h2(kk.z, kk.w));
            float ss = kk.x * kk.x + kk.y * kk.y + kk.z * kk.z + kk.w * kk.w;
            ss += __shfl_xor_sync(~0u, ss, 1);
            ss += __shfl_xor_sync(~0u, ss, 2);
            ss += __shfl_xor_sync(~0u, ss, 4);
            ss += __shfl_xor_sync(~0u, ss, 8);
            if ((t & 15) == 0) s[KH + l] = fmaf(-0.5f * SC2, ss, -stab);
            float4 vv = *reinterpret_cast<const float4*>(V_ + off);
            *reinterpret_cast<uint2*>(su + KVo + l * 36 + 2 * c4) =
                make_uint2(h2(vv.x, vv.y), h2(vv.z, vv.w));
        }
        __syncthreads();

        // ---- GEMM1 both halves + epilogue (k' -> KP[l][f], vectorized) ----
#pragma unroll
        for (int h = 0; h < 2; ++h) {
            const uint32_t bW = sb + (KW + (h * 128 + nb + brow) * 36) * 4 + bko;
            float c[2][4][4] = {};
#pragma unroll
            for (int ks = 0; ks < 4; ++ks) {
                uint32_t a0[4], a1[4], b0[4], b1[4];
                ldsm4(a0, aA + ks * 32);
                ldsm4(a1, aA + 16 * 144 + ks * 32);
                ldsm4(b0, bW + ks * 32);
                ldsm4(b1, bW + 2304 + ks * 32);
                mma16(c[0][0], a0, b0); mma16(c[0][1], a0, b0 + 2);
                mma16(c[0][2], a0, b1); mma16(c[0][3], a0, b1 + 2);
                mma16(c[1][0], a1, b0); mma16(c[1][1], a1, b0 + 2);
                mma16(c[1][2], a1, b1); mma16(c[1][3], a1, b1 + 2);
            }
#pragma unroll
            for (int mi = 0; mi < 2; ++mi) {
                int r0 = mb + mi * 16 + qrow;
                float eb0 = s[KH + r0], eb1 = s[KH + r0 + 8];
#pragma unroll
                for (int ni = 0; ni < 4; ++ni) {
                    int wcol = h * 64 + (nb >> 1) + ni * 4 + qc;   // word = f/2
                    su[KP + r0 * 132 + wcol] =
                        h2(INVSQM * (__expf(fmaf(SCALE, c[mi][ni][0], eb0)) + CEPS),
                           INVSQM * (__expf(fmaf(SCALE, c[mi][ni][1], eb0)) + CEPS));
                    su[KP + (r0 + 8) * 132 + wcol] =
                        h2(INVSQM * (__expf(fmaf(SCALE, c[mi][ni][2], eb1)) + CEPS),
                           INVSQM * (__expf(fmaf(SCALE, c[mi][ni][3], eb1)) + CEPS));
                }
            }
        }
        __syncthreads();
        // ---- GEMM2: KV[f,72] += k'^T x Vaug; B loaded once per ks ----
#pragma unroll
        for (int ks = 0; ks < 4; ++ks) {
            uint32_t a0[4], a1[4], bv0[4], bv1[4], bv2[4], bv3[4], bv8[2];
            ldsm4t(a0, aP + ks * 8448);            // f-tile fb (f 0..127 range)
            ldsm4t(a1, aP + 256 + ks * 8448);      // f-tile 128+fb
            ldsm4t(bv0, bV + ks * 2304);
            ldsm4t(bv1, bV + 32 + ks * 2304);
            ldsm4t(bv2, bV + 64 + ks * 2304);
            ldsm4t(bv3, bV + 96 + ks * 2304);
            ldsm2t(bv8, bV8 + ks * 2304);
            mma16(kvacc[0][0], a0, bv0); mma16(kvacc[0][1], a0, bv0 + 2);
            mma16(kvacc[0][2], a0, bv1); mma16(kvacc[0][3], a0, bv1 + 2);
            mma16(kvacc[0][4], a0, bv2); mma16(kvacc[0][5], a0, bv2 + 2);
            mma16(kvacc[0][6], a0, bv3); mma16(kvacc[0][7], a0, bv3 + 2);
            mma16(kvacc[0][8], a0, bv8);
            mma16(kvacc[1][0], a1, bv0); mma16(kvacc[1][1], a1, bv0 + 2);
            mma16(kvacc[1][2], a1, bv1); mma16(kvacc[1][3], a1, bv1 + 2);
            mma16(kvacc[1][4], a1, bv2); mma16(kvacc[1][5], a1, bv2 + 2);
            mma16(kvacc[1][6], a1, bv3); mma16(kvacc[1][7], a1, bv3 + 2);
            mma16(kvacc[1][8], a1, bv8);
        }
        __syncthreads();
    }
    float* g = g_kv + (size_t)bh * 256 * 72;
#pragma unroll
    for (int h = 0; h < 2; ++h)
#pragma unroll
        for (int ni = 0; ni < 9; ++ni) {
            int f0 = h * 128 + fb + qrow, d0 = ni * 8 + qc * 2;
            atomicAdd(g + f0 * 72 + d0, kvacc[h][ni][0]);
            atomicAdd(g + f0 * 72 + d0 + 1, kvacc[h][ni][1]);
            atomicAdd(g + (f0 + 8) * 72 + d0, kvacc[h][ni][2]);
            atomicAdd(g + (f0 + 8) * 72 + d0 + 1, kvacc[h][ni][3]);
        }
}

// ---------------------------------------------------------------------------
// favor_q: GEMM1 C-frags -> fp16 A-frags in registers (q' never in smem).
// ---------------------------------------------------------------------------
__global__ __launch_bounds__(256, 2) void favor_q(
    const float* __restrict__ Q_, const float* __restrict__ W_,
    float* __restrict__ O_) {
    extern __shared__ float s[];
    uint32_t* su = reinterpret_cast<uint32_t*>(s);
    __half* sh16 = reinterpret_cast<__half*>(s);
    const uint32_t sb = (uint32_t)__cvta_generic_to_shared(s);
    const int t = threadIdx.x, w = t >> 5, lane = t & 31;
    const int qrow = lane >> 2, qc = lane & 3;
    const int bh = blockIdx.x, bb = bh >> 4, hh = bh & 15;
#pragma unroll
    for (int i = 0; i < 16; ++i) {
        int idx = t + i * 256, f = idx >> 4, c4 = idx & 15;
        float4 wv = *reinterpret_cast<const float4*>(W_ + f * 64 + c4 * 4);
        *reinterpret_cast<uint2*>(su + QW + f * 36 + 2 * c4) =
            make_uint2(h2(wv.x, wv.y), h2(wv.z, wv.w));
    }
    {   // KV^T [d'][f] fp16, natural f order
        const float* g = g_kv + (size_t)bh * 256 * 72;
        for (int i = t; i < 256 * 72; i += 256) {
            int f = i / 72, d = i - f * 72;
            sh16[(QKV + d * 132) * 2 + f] = __float2half(g[i]);
        }
    }
    __syncthreads();
    const int ms = (w & 3) * 16, fg = w >> 2;
    const int lrow = lane & 15;
    const int khi = (lane >> 4) * 16;
    const int bko = (lane & 8) ? 16 : 0;
    const int brow = (lane & 7) + ((lane & 16) ? 8 : 0);
    const uint32_t aQ = sb + (QT + (ms + lrow) * 36) * 4 + khi;
    const uint32_t bW = sb + (QW + (fg * 128 + brow) * 36) * 4 + bko;
    const uint32_t bK = sb + (QKV + brow * 132) * 4 + fg * 256 + bko;
    const uint32_t bK8 = sb + (QKV + (64 + (lane & 7)) * 132) * 4 + fg * 256 + bko;

    for (int ti = 0; ti < 8; ++ti) {
        const int l0 = ((int)blockIdx.y * 8 + ti) * 64;
#pragma unroll
        for (int i = 0; i < 4; ++i) {
            int idx = t + i * 256, l = idx >> 4, c4 = idx & 15;
            size_t off = ((size_t)(bb * L_ + l0 + l)) * D_ + hh * 64 + c4 * 4;
            float4 qq = *reinterpret_cast<const float4*>(Q_ + off);
            *reinterpret_cast<uint2*>(su + QT + l * 36 + 2 * c4) =
                make_uint2(h2(qq.x, qq.y), h2(qq.z, qq.w));
        }
        __syncthreads();
        // ---- GEMM1: S(16m x 128n per warp), n-range fg*128 ----
        float c[16][4] = {};
#pragma unroll
        for (int ks = 0; ks < 4; ++ks) {
            uint32_t a2[4];
            ldsm4(a2, aQ + ks * 32);
#pragma unroll
            for (int p = 0; p < 8; ++p) {
                uint32_t bp[4];
                ldsm4(bp, bW + p * 2304 + ks * 32);
                mma16(c[2 * p], a2, bp);
                mma16(c[2 * p + 1], a2, bp + 2);
            }
        }
        // ---- epilogue: exp + pack C pairs -> fp16 A-frags (k=16 each) ----
        uint32_t cu[8][4];
#pragma unroll
        for (int j = 0; j < 8; ++j) {
            float v00 = INVSQM * (__expf(SCALE * c[2 * j][0]) + CEPS);
            float v01 = INVSQM * (__expf(SCALE * c[2 * j][1]) + CEPS);
            float v02 = INVSQM * (__expf(SCALE * c[2 * j][2]) + CEPS);
            float v03 = INVSQM * (__expf(SCALE * c[2 * j][3]) + CEPS);
            float v10 = INVSQM * (__expf(SCALE * c[2 * j + 1][0]) + CEPS);
            float v11 = INVSQM * (__expf(SCALE * c[2 * j + 1][1]) + CEPS);
            float v12 = INVSQM * (__expf(SCALE * c[2 * j + 1][2]) + CEPS);
            float v13 = INVSQM * (__expf(SCALE * c[2 * j + 1][3]) + CEPS);
            cu[j][0] = h2(v00, v01);
            cu[j][1] = h2(v02, v03);
            cu[j][2] = h2(v10, v11);
            cu[j][3] = h2(v12, v13);
        }
        // ---- GEMM3: out[16m x 72] partial over f-range fg*128 ----
        float o[9][4] = {};
#pragma unroll
        for (int j = 0; j < 8; ++j) {
            uint32_t bv0[4], bv1[4], bv2[4], bv3[4], bv8[2];
            ldsm4(bv0, bK + j * 32);
            ldsm4(bv1, bK + 8448 + j * 32);
            ldsm4(bv2, bK + 16896 + j * 32);
            ldsm4(bv3, bK + 25344 + j * 32);
            ldsm2(bv8, bK8 + j * 32);
            mma16(o[0], cu[j], bv0); mma16(o[1], cu[j], bv0 + 2);
            mma16(o[2], cu[j], bv1); mma16(o[3], cu[j], bv1 + 2);
            mma16(o[4], cu[j], bv2); mma16(o[5], cu[j], bv2 + 2);
            mma16(o[6], cu[j], bv3); mma16(o[7], cu[j], bv3 + 2);
            mma16(o[8], cu[j], bv8);
        }
        __syncthreads();
        if (fg == 1) {
            int r0 = ms + qrow;
#pragma unroll
            for (int ni = 0; ni < 9; ++ni) {
                int col = ni * 8 + 2 * qc;
                *reinterpret_cast<float2*>(s + QOP + r0 * 72 + col) =
                    make_float2(o[ni][0], o[ni][1]);
                *reinterpret_cast<float2*>(s + QOP + (r0 + 8) * 72 + col) =
                    make_float2(o[ni][2], o[ni][3]);
            }
        }
        __syncthreads();
        if (fg == 0) {
            int r0 = ms + qrow;
#pragma unroll
            for (int ni = 0; ni < 9; ++ni) {
                int col = ni * 8 + 2 * qc;
                float2 p0 = *reinterpret_cast<const float2*>(s + QOP + r0 * 72 + col);
                float2 p1 = *reinterpret_cast<const float2*>(s + QOP + (r0 + 8) * 72 + col);
                o[ni][0] += p0.x; o[ni][1] += p0.y;
                o[ni][2] += p1.x; o[ni][3] += p1.y;
            }
            float den0 = __shfl_sync(~0u, o[8][0], lane & ~3);
            float den1 = __shfl_sync(~0u, o[8][2], lane & ~3);
            if (fabsf(den0) <= CEPS) den0 += 2.f * CEPS;
            if (fabsf(den1) <= CEPS) den1 += 2.f * CEPS;
            float inv0 = 1.f / den0, inv1 = 1.f / den1;
            float* op0 = O_ + ((size_t)(bb * L_ + l0 + r0)) * D_ + hh * 64;
            float* op1 = op0 + 8 * D_;
#pragma unroll
            for (int ni = 0; ni < 8; ++ni) {
                int col = ni * 8 + 2 * qc;
                *reinterpret_cast<float2*>(op0 + col) =
                    make_float2(o[ni][0] * inv0, o[ni][1] * inv0);
                *reinterpret_cast<float2*>(op1 + col) =
                    make_float2(o[ni][2] * inv1, o[ni][3] * inv1);
            }
        }
    }
}

// ---------------------------------------------------------------------------
extern "C" void kernel_launch(void* const* d_in, const int* in_sizes, int n_in,
                              void* d_out, int out_size) {
    const float* q = (const float*)d_in[0];
    const float* k = (const float*)d_in[1];
    const float* v = (const float*)d_in[2];
    const float* w = (const float*)d_in[3];
    float* out = (float*)d_out;

    cudaFuncSetAttribute(favor_k, cudaFuncAttributeMaxDynamicSharedMemorySize, KFL * 4);
    cudaFuncSetAttribute(favor_q, cudaFuncAttributeMaxDynamicSharedMemorySize, QFL * 4);

    init_kernel<<<1, 1>>>();
    min_kernel<<<1024, 256>>>(k);
    favor_k<<<dim3(64, 8), 256, KFL * 4>>>(k, v, w);
    favor_q<<<dim3(64, 8), 256, QFL * 4>>>(q, w, out);
}